// round 11
// baseline (speedup 1.0000x reference)
#include <cuda_runtime.h>
#include <cuda_bf16.h>
#include <cstdint>

// ---------------- problem constants ----------------
#define BB    64
#define NSEQ  1024
#define NTOK  100
#define DIMC  256
#define NHEAD 8
#define HKV   640
#define PROJIN 1512
#define KEFF  1312
#define EPSV  1e-5f
#define MTOT  (BB*NSEQ)

// ---------------- scratch ----------------
__device__ float g_q[NTOK * 128];
__device__ float g_k[(size_t)MTOT * 128];
__device__ __nv_bfloat16 g_xh[(size_t)MTOT * DIMC];
__device__ __nv_bfloat16 g_xl[(size_t)MTOT * DIMC];
__device__ __nv_bfloat16 g_kwh[HKV * DIMC];
__device__ __nv_bfloat16 g_kwl[HKV * DIMC];
__device__ __nv_bfloat16 g_pwh[DIMC * KEFF];
__device__ __nv_bfloat16 g_pwl[DIMC * KEFF];
__device__ __nv_bfloat16 g_vh[(size_t)MTOT * 512];                  // hi of hswish(v), (bn, h*64+d)
__device__ __nv_bfloat16 g_vl[(size_t)MTOT * 512];                  // lo
__device__ __nv_bfloat16 g_ah[(size_t)BB * NHEAD * NTOK * NSEQ];    // hi of hswish(p), (b,h,t,n)
__device__ __nv_bfloat16 g_al[(size_t)BB * NHEAD * NTOK * NSEQ];    // lo
__device__ float g_kvs[HKV], g_kvt[HKV];
__device__ float g_qsA[128], g_qtA[128];
__device__ float g_psA[DIMC], g_ptA[DIMC];

__device__ __forceinline__ float hswish(float y) {
    return y * fminf(fmaxf(y + 3.f, 0.f), 6.f) * (1.f / 6.f);
}
__device__ __forceinline__ uint32_t smem_u32(const void* p) {
    uint32_t a;
    asm("{ .reg .u64 t; cvta.to.shared.u64 t, %1; cvt.u32.u64 %0, t; }" : "=r"(a) : "l"(p));
    return a;
}
__device__ __forceinline__ void split4(float4 v, unsigned long long& H, unsigned long long& L) {
    float f[4] = {v.x, v.y, v.z, v.w};
    unsigned long long h = 0, l = 0;
#pragma unroll
    for (int i = 0; i < 4; i++) {
        __nv_bfloat16 hb = __float2bfloat16_rn(f[i]);
        float r = f[i] - __bfloat162float(hb);
        __nv_bfloat16 lb = __float2bfloat16_rn(r);
        h |= (unsigned long long)__bfloat16_as_ushort(hb) << (16 * i);
        l |= (unsigned long long)__bfloat16_as_ushort(lb) << (16 * i);
    }
    H = h; L = l;
}
__device__ __forceinline__ void splitbf(float y, unsigned short& hu, unsigned short& lu) {
    __nv_bfloat16 hb = __float2bfloat16_rn(y);
    float r = y - __bfloat162float(hb);
    __nv_bfloat16 lb = __float2bfloat16_rn(r);
    hu = __bfloat16_as_ushort(hb); lu = __bfloat16_as_ushort(lb);
}

// ---------------- warp-mma + cp.async primitives (baseline PTX, sm_80+) ----------------
__device__ __forceinline__ void ldsm4(uint32_t addr, uint32_t* r) {
    asm volatile("ldmatrix.sync.aligned.m8n8.x4.shared.b16 {%0,%1,%2,%3}, [%4];"
                 : "=r"(r[0]), "=r"(r[1]), "=r"(r[2]), "=r"(r[3]) : "r"(addr));
}
__device__ __forceinline__ void mma16816(float* c, const uint32_t* a, uint32_t b0, uint32_t b1) {
    asm volatile("mma.sync.aligned.m16n8k16.row.col.f32.bf16.bf16.f32 "
                 "{%0,%1,%2,%3}, {%4,%5,%6,%7}, {%8,%9}, {%0,%1,%2,%3};"
                 : "+f"(c[0]), "+f"(c[1]), "+f"(c[2]), "+f"(c[3])
                 : "r"(a[0]), "r"(a[1]), "r"(a[2]), "r"(a[3]), "r"(b0), "r"(b1));
}
__device__ __forceinline__ void cp16(uint32_t s, const void* g) {
    asm volatile("cp.async.cg.shared.global [%0], [%1], 16;" :: "r"(s), "l"(g));
}
#define CP_COMMIT() asm volatile("cp.async.commit_group;" ::: "memory")
#define CP_WAIT0()  asm volatile("cp.async.wait_group 0;" ::: "memory")
#define CP_WAIT1()  asm volatile("cp.async.wait_group 1;" ::: "memory")

#define PITCH 80
// kv stage: AH@0, AL@10240, BH@20480, BL@30720 -> 40960; 3 stages
#define STG_KV   40960
#define DSMEM_KV (3*STG_KV)
// proj stage: AH@0 (128r), AL@10240, BH@20480 (256r), BL@40960 -> 61440; 3 stages
#define STG_PJ   61440
#define DSMEM_PJ (3*STG_PJ)

// warp tile 32x64 (kv), acc c[2][8][4]
__device__ __forceinline__ void mma_chunk32(uint32_t sb, int wm, int wn,
                                            int arow, int acol, int brow, int bcol,
                                            float c[2][8][4]) {
#pragma unroll
    for (int ks = 0; ks < 32; ks += 16) {
        uint32_t ah0[4], ah1[4], al0[4], al1[4];
        uint32_t aoff = (uint32_t)((wm * 32 + arow) * PITCH + (ks + acol) * 2);
        ldsm4(sb + aoff, ah0);
        ldsm4(sb + aoff + 16 * PITCH, ah1);
        ldsm4(sb + 10240 + aoff, al0);
        ldsm4(sb + 10240 + aoff + 16 * PITCH, al1);
#pragma unroll
        for (int np = 0; np < 4; np++) {
            uint32_t bh[4], bl[4];
            uint32_t boff = (uint32_t)((wn * 64 + np * 16 + brow) * PITCH + (ks + bcol) * 2);
            ldsm4(sb + 20480 + boff, bh);
            ldsm4(sb + 30720 + boff, bl);
            mma16816(c[0][np * 2],     ah0, bh[0], bh[1]);
            mma16816(c[1][np * 2],     ah1, bh[0], bh[1]);
            mma16816(c[0][np * 2 + 1], ah0, bh[2], bh[3]);
            mma16816(c[1][np * 2 + 1], ah1, bh[2], bh[3]);
            mma16816(c[0][np * 2],     al0, bh[0], bh[1]);
            mma16816(c[1][np * 2],     al1, bh[0], bh[1]);
            mma16816(c[0][np * 2 + 1], al0, bh[2], bh[3]);
            mma16816(c[1][np * 2 + 1], al1, bh[2], bh[3]);
            mma16816(c[0][np * 2],     ah0, bl[0], bl[1]);
            mma16816(c[1][np * 2],     ah1, bl[0], bl[1]);
            mma16816(c[0][np * 2 + 1], ah0, bl[2], bl[3]);
            mma16816(c[1][np * 2 + 1], ah1, bl[2], bl[3]);
        }
    }
}

// warp tile 64x64 (proj), acc c[4][8][4]
__device__ __forceinline__ void mma_chunk64(uint32_t sb, int wm, int wn,
                                            int arow, int acol, int brow, int bcol,
                                            float c[4][8][4]) {
#pragma unroll
    for (int ks = 0; ks < 32; ks += 16) {
        uint32_t ah[4][4], al[4][4];
#pragma unroll
        for (int mi = 0; mi < 4; mi++) {
            uint32_t aoff = (uint32_t)((wm * 64 + mi * 16 + arow) * PITCH + (ks + acol) * 2);
            ldsm4(sb + aoff, ah[mi]);
            ldsm4(sb + 10240 + aoff, al[mi]);
        }
#pragma unroll
        for (int np = 0; np < 4; np++) {
            uint32_t bh[4], bl[4];
            uint32_t boff = (uint32_t)((wn * 64 + np * 16 + brow) * PITCH + (ks + bcol) * 2);
            ldsm4(sb + 20480 + boff, bh);
            ldsm4(sb + 40960 + boff, bl);
#pragma unroll
            for (int mi = 0; mi < 4; mi++) {
                mma16816(c[mi][np * 2],     ah[mi], bh[0], bh[1]);
                mma16816(c[mi][np * 2 + 1], ah[mi], bh[2], bh[3]);
                mma16816(c[mi][np * 2],     al[mi], bh[0], bh[1]);
                mma16816(c[mi][np * 2 + 1], al[mi], bh[2], bh[3]);
                mma16816(c[mi][np * 2],     ah[mi], bl[0], bl[1]);
                mma16816(c[mi][np * 2 + 1], ah[mi], bl[2], bl[3]);
            }
        }
    }
}

// ---------------- prep kernels ----------------
__global__ void k_prep_bn(const float* kg, const float* kb, const float* km, const float* kv,
                          const float* qg, const float* qb, const float* qm, const float* qv,
                          const float* pg, const float* pb, const float* pm, const float* pv) {
    int i = blockIdx.x * 256 + threadIdx.x;
    if (i < HKV) {
        float s = kg[i] * rsqrtf(kv[i] + EPSV);
        g_kvs[i] = s; g_kvt[i] = kb[i] - km[i] * s;
    } else if (i < HKV + 128) {
        int j = i - HKV;
        float s = qg[j] * rsqrtf(qv[j] + EPSV);
        g_qsA[j] = s; g_qtA[j] = qb[j] - qm[j] * s;
    } else if (i < HKV + 128 + DIMC) {
        int j = i - HKV - 128;
        float s = pg[j] * rsqrtf(pv[j] + EPSV);
        g_psA[j] = s; g_ptA[j] = pb[j] - pm[j] * s;
    }
}
__global__ void k_split_x(const float* __restrict__ src) {
    int i = blockIdx.x * 256 + threadIdx.x;
    if (i >= MTOT * DIMC / 4) return;
    float4 v = ((const float4*)src)[i];
    unsigned long long H, L; split4(v, H, L);
    ((unsigned long long*)g_xh)[i] = H;
    ((unsigned long long*)g_xl)[i] = L;
}
__global__ void k_split_kw(const float* __restrict__ src) {
    int i = blockIdx.x * 256 + threadIdx.x;
    if (i >= HKV * DIMC / 4) return;
    float4 v = ((const float4*)src)[i];
    unsigned long long H, L; split4(v, H, L);
    ((unsigned long long*)g_kwh)[i] = H;
    ((unsigned long long*)g_kwl)[i] = L;
}
__global__ void k_split_pw(const float* __restrict__ src) {
    int i = blockIdx.x * 256 + threadIdx.x;
    if (i >= DIMC * (KEFF / 4)) return;
    int r = i / (KEFF / 4), c = i % (KEFF / 4);
    float4 v = *(const float4*)(src + (size_t)r * PROJIN + c * 4);
    unsigned long long H, L; split4(v, H, L);
    ((unsigned long long*)g_pwh)[i] = H;
    ((unsigned long long*)g_pwl)[i] = L;
}

// ---------------- kernel: q projection + BN ----------------
__global__ void k_qproj(const float* __restrict__ text, const float* __restrict__ qw) {
    int o = blockIdx.x * blockDim.x + threadIdx.x;
    if (o >= NTOK * 128) return;
    int t = o >> 7, col = o & 127;
    const float4* tr = (const float4*)(text + t * DIMC);
    const float4* wr = (const float4*)(qw + col * DIMC);
    float acc = 0.f;
#pragma unroll 16
    for (int k = 0; k < DIMC / 4; k++) {
        float4 a = tr[k], w = wr[k];
        acc += a.x * w.x + a.y * w.y + a.z * w.z + a.w * w.w;
    }
    g_q[o] = acc * g_qsA[col] + g_qtA[col];
}

// ---------------- kernel: kv GEMM (256 thr, warp 32x64, 3-stage cp.async) ----------------
__global__ __launch_bounds__(256) void k_kv_mma() {
    extern __shared__ __align__(128) unsigned char sm[];
    uint32_t s0 = smem_u32(sm);
    const int tid = threadIdx.x, lane = tid & 31, wid = tid >> 5;
    const int m0 = blockIdx.y * 128, n0 = blockIdx.x * 128;
    const int wm = wid >> 1, wn = wid & 1;
    const int arow = ((lane >> 3) & 1) * 8 + (lane & 7), acol = (lane >> 4) * 8;
    const int brow = (lane >> 4) * 8 + (lane & 7), bcol = ((lane >> 3) & 1) * 8;
    const __nv_bfloat16* pAH = g_xh + (size_t)m0 * DIMC;
    const __nv_bfloat16* pAL = g_xl + (size_t)m0 * DIMC;
    const __nv_bfloat16* pBH = g_kwh + (size_t)n0 * DIMC;
    const __nv_bfloat16* pBL = g_kwl + (size_t)n0 * DIMC;
    float c[2][8][4] = {};

    auto LOAD = [&](int kc) {
        const int kt = kc * 32;
        const uint32_t sb = s0 + (kc % 3) * STG_KV;
#pragma unroll
        for (int i = 0; i < 8; i++) {
            int item = tid + i * 256;
            int ab = item >> 10, arr = (item >> 9) & 1, row = (item >> 2) & 127, c16 = item & 3;
            const __nv_bfloat16* src = ab ? (arr ? pBL : pBH) : (arr ? pAL : pAH);
            src += (size_t)row * DIMC + kt + c16 * 8;
            cp16(sb + ab * 20480 + arr * 10240 + row * PITCH + c16 * 16, src);
        }
    };

    LOAD(0); CP_COMMIT();
    LOAD(1); CP_COMMIT();
#pragma unroll 1
    for (int kc = 0; kc < 8; kc++) {
        if (kc < 7) { CP_WAIT1(); } else { CP_WAIT0(); }
        __syncthreads();
        mma_chunk32(s0 + (kc % 3) * STG_KV, wm, wn, arow, acol, brow, bcol, c);
        if (kc + 2 < 8) { LOAD(kc + 2); CP_COMMIT(); }
    }

    unsigned short* VH = (unsigned short*)g_vh;
    unsigned short* VL = (unsigned short*)g_vl;
#pragma unroll
    for (int mi = 0; mi < 2; mi++) {
        int row = m0 + wm * 32 + mi * 16 + (lane >> 2);
#pragma unroll
        for (int ni = 0; ni < 8; ni++) {
#pragma unroll
            for (int cc = 0; cc < 2; cc++) {
                int col = n0 + wn * 64 + ni * 8 + (lane & 3) * 2 + cc;
                float s = g_kvs[col], t = g_kvt[col];
                int h = col / 80, r = col % 80;
                float y0 = c[mi][ni][cc] * s + t;
                float y1 = c[mi][ni][cc + 2] * s + t;
                if (r < 16) {
                    g_k[(size_t)row * 128 + h * 16 + r] = y0;
                    g_k[(size_t)(row + 8) * 128 + h * 16 + r] = y1;
                } else {
                    unsigned short hu, lu;
                    size_t i0 = (size_t)row * 512 + h * 64 + (r - 16);
                    size_t i1 = (size_t)(row + 8) * 512 + h * 64 + (r - 16);
                    splitbf(hswish(y0), hu, lu); VH[i0] = hu; VL[i0] = lu;
                    splitbf(hswish(y1), hu, lu); VH[i1] = hu; VL[i1] = lu;
                }
            }
        }
    }
}

// ---------------- kernel: attention + softmax + hswish -> split bf16 (coalesced (b,h,t,n)) ----------------
__global__ __launch_bounds__(1024) void k_attn(const float* __restrict__ biases) {
    const int h = blockIdx.x, b = blockIdx.y;
    const int tid = threadIdx.x;
    __shared__ float qs[NTOK * 16];
    __shared__ float bias_s[3200];
    __shared__ float red[32 * 10];
    __shared__ float bcast[10];

    float kr[16];
    const float4* kp = (const float4*)(g_k + (size_t)(b * NSEQ + tid) * 128 + h * 16);
#pragma unroll
    for (int i = 0; i < 4; i++) {
        float4 v = kp[i];
        kr[i * 4] = v.x; kr[i * 4 + 1] = v.y; kr[i * 4 + 2] = v.z; kr[i * 4 + 3] = v.w;
    }
    for (int i = tid; i < NTOK * 16; i += 1024) qs[i] = g_q[(i >> 4) * 128 + (i & 15) + h * 16];
    for (int i = tid; i < 3200; i += 1024) bias_s[i] = biases[h * 10000 + i];
    __syncthreads();

    const int p2x = tid >> 5, p2y = tid & 31;
    const int warp = tid >> 5, lane = tid & 31;
    unsigned short* AH = (unsigned short*)g_ah;
    unsigned short* AL = (unsigned short*)g_al;
    size_t obase = ((size_t)(b * NHEAD + h) * NTOK) * NSEQ + tid;

    for (int t0 = 0; t0 < NTOK; t0 += 10) {
        float e[10];
#pragma unroll
        for (int cch = 0; cch < 10; cch++) {
            int t = t0 + cch;
            float logit = 0.f;
#pragma unroll
            for (int d = 0; d < 16; d++) logit += qs[t * 16 + d] * kr[d];
            int dy = t - p2y; if (dy < 0) dy = -dy;
            logit = logit * 0.25f + bias_s[p2x * 100 + dy];
            float ex = __expf(logit);
            e[cch] = ex;
            float s = ex;
#pragma unroll
            for (int o = 16; o > 0; o >>= 1) s += __shfl_xor_sync(0xffffffffu, s, o);
            if (lane == 0) red[warp * 10 + cch] = s;
        }
        __syncthreads();
        if (warp == 0) {
#pragma unroll
            for (int cch = 0; cch < 10; cch++) {
                float v = red[lane * 10 + cch];
#pragma unroll
                for (int o = 16; o > 0; o >>= 1) v += __shfl_xor_sync(0xffffffffu, v, o);
                if (lane == 0) bcast[cch] = v;
            }
        }
        __syncthreads();
#pragma unroll
        for (int cch = 0; cch < 10; cch++) {
            float p = e[cch] * __frcp_rn(bcast[cch]);
            float y = p * (p + 3.f) * (1.f / 6.f);
            unsigned short hu, lu; splitbf(y, hu, lu);
            size_t idx = obase + (size_t)(t0 + cch) * NSEQ;
            AH[idx] = hu; AL[idx] = lu;
        }
    }
}

// ---------------- kernel: proj GEMM (CTA 128x256, warp 64x64, 3-stage cp.async) ----------------
__global__ __launch_bounds__(256) void k_proj_mma(float* __restrict__ out) {
    extern __shared__ __align__(128) unsigned char sm[];
    uint32_t s0 = smem_u32(sm);
    const int tid = threadIdx.x, lane = tid & 31, wid = tid >> 5;
    const int m0 = blockIdx.x * 128;
    const int b = m0 >> 10, nbase = m0 & 1023;
    const int rowbase = b * 800;
    const int wm = wid >> 2, wn = wid & 3;            // 2 x 4 warps, warp tile 64M x 64N
    const int arow = ((lane >> 3) & 1) * 8 + (lane & 7), acol = (lane >> 4) * 8;
    const int brow = (lane >> 4) * 8 + (lane & 7), bcol = ((lane >> 3) & 1) * 8;
    const __nv_bfloat16* pAH = g_vh + (size_t)m0 * 512;
    const __nv_bfloat16* pAL = g_vl + (size_t)m0 * 512;
    const __nv_bfloat16* pBH = g_pwh;                 // full 256 x KEFF
    const __nv_bfloat16* pBL = g_pwl;
    const unsigned short* GAH = (const unsigned short*)g_ah;
    const unsigned short* GAL = (const unsigned short*)g_al;
    float c[4][8][4] = {};

    auto LOAD = [&](int kc) {
        const int kt = kc * 32;
        const uint32_t sb = s0 + (kc % 3) * STG_PJ;
        unsigned char* smb = sm + (kc % 3) * STG_PJ;
        // B tiles: 256 rows x 64 cols, hi+lo -> 2048 cp16
#pragma unroll
        for (int i = 0; i < 8; i++) {
            int item = tid + i * 256;
            int arr = item >> 10, row = (item >> 2) & 255, c16 = item & 3;
            const __nv_bfloat16* src = (arr ? pBL : pBH) + (size_t)row * KEFF + kt + c16 * 8;
            cp16(sb + 20480 + arr * 20480 + row * PITCH + c16 * 16, src);
        }
        if (kt < 512) {
            // v features: 128 rows x 64 cols, hi+lo -> 1024 cp16
#pragma unroll
            for (int i = 0; i < 4; i++) {
                int item = tid + i * 256;
                int arr = item >> 9, row = (item >> 2) & 127, c16 = item & 3;
                const __nv_bfloat16* src = (arr ? pAL : pAH) + (size_t)row * 512 + kt + c16 * 8;
                cp16(sb + arr * 10240 + row * PITCH + c16 * 16, src);
            }
        } else {
            // attn features: coalesced read + 2B transpose into SMEM
            const int kloc = kt - 512;
#pragma unroll
            for (int i = 0; i < 8; i++) {
                int item = tid + i * 256;
                int krow = item >> 6, nn = (item & 63) * 2;
                size_t idx = (size_t)(rowbase + kloc + krow) * NSEQ + nbase + nn;
                uint32_t vh = *(const uint32_t*)(GAH + idx);
                uint32_t vl = *(const uint32_t*)(GAL + idx);
                *(unsigned short*)(smb + nn * PITCH + krow * 2)               = (unsigned short)vh;
                *(unsigned short*)(smb + (nn + 1) * PITCH + krow * 2)         = (unsigned short)(vh >> 16);
                *(unsigned short*)(smb + 10240 + nn * PITCH + krow * 2)       = (unsigned short)vl;
                *(unsigned short*)(smb + 10240 + (nn + 1) * PITCH + krow * 2) = (unsigned short)(vl >> 16);
            }
        }
    };

    LOAD(0); CP_COMMIT();
    LOAD(1); CP_COMMIT();
#pragma unroll 1
    for (int kc = 0; kc < 41; kc++) {
        if (kc < 40) { CP_WAIT1(); } else { CP_WAIT0(); }
        __syncthreads();
        mma_chunk64(s0 + (kc % 3) * STG_PJ, wm, wn, arow, acol, brow, bcol, c);
        if (kc + 2 < 41) { LOAD(kc + 2); CP_COMMIT(); }
    }

    // epilogue: BN -> out
#pragma unroll
    for (int mi = 0; mi < 4; mi++) {
        int row = m0 + wm * 64 + mi * 16 + (lane >> 2);
#pragma unroll
        for (int ni = 0; ni < 8; ni++) {
#pragma unroll
            for (int cc = 0; cc < 2; cc++) {
                int col = wn * 64 + ni * 8 + (lane & 3) * 2 + cc;
                float s = g_psA[col], t = g_ptA[col];
                out[(size_t)row * DIMC + col]       = c[mi][ni][cc] * s + t;
                out[(size_t)(row + 8) * DIMC + col] = c[mi][ni][cc + 2] * s + t;
            }
        }
    }
}

// ---------------- launch ----------------
extern "C" void kernel_launch(void* const* d_in, const int* in_sizes, int n_in,
                              void* d_out, int out_size) {
    const float* x      = (const float*)d_in[0];
    const float* text   = (const float*)d_in[1];
    const float* kv_w   = (const float*)d_in[2];
    const float* kv_g   = (const float*)d_in[3];
    const float* kv_b   = (const float*)d_in[4];
    const float* kv_m   = (const float*)d_in[5];
    const float* kv_v   = (const float*)d_in[6];
    const float* q_w    = (const float*)d_in[7];
    const float* q_g    = (const float*)d_in[8];
    const float* q_b    = (const float*)d_in[9];
    const float* q_m    = (const float*)d_in[10];
    const float* q_v    = (const float*)d_in[11];
    const float* proj_w = (const float*)d_in[12];
    const float* proj_g = (const float*)d_in[13];
    const float* proj_b = (const float*)d_in[14];
    const float* proj_m = (const float*)d_in[15];
    const float* proj_v = (const float*)d_in[16];
    const float* biases = (const float*)d_in[17];
    float* out = (float*)d_out;

    cudaFuncSetAttribute(k_kv_mma,   cudaFuncAttributeMaxDynamicSharedMemorySize, DSMEM_KV);
    cudaFuncSetAttribute(k_proj_mma, cudaFuncAttributeMaxDynamicSharedMemorySize, DSMEM_PJ);

    k_prep_bn<<<4, 256>>>(kv_g, kv_b, kv_m, kv_v, q_g, q_b, q_m, q_v,
                          proj_g, proj_b, proj_m, proj_v);
    k_split_x<<<(MTOT * DIMC / 4 + 255) / 256, 256>>>(x);
    k_split_kw<<<(HKV * DIMC / 4 + 255) / 256, 256>>>(kv_w);
    k_split_pw<<<(DIMC * (KEFF / 4) + 255) / 256, 256>>>(proj_w);
    k_qproj<<<50, 256>>>(text, q_w);
    k_kv_mma<<<dim3(HKV / 128, MTOT / 128), 256, DSMEM_KV>>>();
    k_attn<<<dim3(NHEAD, BB), 1024>>>(biases);
    k_proj_mma<<<MTOT / 128, 256, DSMEM_PJ>>>(out);
}

// round 12
// speedup vs baseline: 1.1633x; 1.1633x over previous
#include <cuda_runtime.h>
#include <cuda_bf16.h>
#include <cstdint>

// ---------------- problem constants ----------------
#define BB    64
#define NSEQ  1024
#define NTOK  100
#define DIMC  256
#define NHEAD 8
#define HKV   640
#define PROJIN 1512
#define KEFF  1312
#define EPSV  1e-5f
#define MTOT  (BB*NSEQ)

// ---------------- scratch ----------------
__device__ float g_q[NTOK * 128];
__device__ float g_k[(size_t)MTOT * 128];
__device__ __nv_bfloat16 g_xh[(size_t)MTOT * DIMC];
__device__ __nv_bfloat16 g_xl[(size_t)MTOT * DIMC];
__device__ __nv_bfloat16 g_kwh[HKV * DIMC];
__device__ __nv_bfloat16 g_kwl[HKV * DIMC];
__device__ __nv_bfloat16 g_pwh[DIMC * KEFF];
__device__ __nv_bfloat16 g_pwl[DIMC * KEFF];
__device__ __nv_bfloat16 g_vh[(size_t)MTOT * 512];                  // hi of hswish(v)
__device__ __nv_bfloat16 g_vl[(size_t)MTOT * 512];                  // lo
__device__ __nv_bfloat16 g_ah[(size_t)BB * NHEAD * NTOK * NSEQ];    // hswish(p), single bf16, (b,h,t,n)
__device__ float g_kvs[HKV], g_kvt[HKV];
__device__ float g_qsA[128], g_qtA[128];
__device__ float g_psA[DIMC], g_ptA[DIMC];

__device__ __forceinline__ float hswish(float y) {
    return y * fminf(fmaxf(y + 3.f, 0.f), 6.f) * (1.f / 6.f);
}
__device__ __forceinline__ uint32_t smem_u32(const void* p) {
    uint32_t a;
    asm("{ .reg .u64 t; cvta.to.shared.u64 t, %1; cvt.u32.u64 %0, t; }" : "=r"(a) : "l"(p));
    return a;
}
__device__ __forceinline__ void split4(float4 v, unsigned long long& H, unsigned long long& L) {
    float f[4] = {v.x, v.y, v.z, v.w};
    unsigned long long h = 0, l = 0;
#pragma unroll
    for (int i = 0; i < 4; i++) {
        __nv_bfloat16 hb = __float2bfloat16_rn(f[i]);
        float r = f[i] - __bfloat162float(hb);
        __nv_bfloat16 lb = __float2bfloat16_rn(r);
        h |= (unsigned long long)__bfloat16_as_ushort(hb) << (16 * i);
        l |= (unsigned long long)__bfloat16_as_ushort(lb) << (16 * i);
    }
    H = h; L = l;
}
__device__ __forceinline__ void splitbf(float y, unsigned short& hu, unsigned short& lu) {
    __nv_bfloat16 hb = __float2bfloat16_rn(y);
    float r = y - __bfloat162float(hb);
    __nv_bfloat16 lb = __float2bfloat16_rn(r);
    hu = __bfloat16_as_ushort(hb); lu = __bfloat16_as_ushort(lb);
}

// ---------------- warp-mma + cp.async primitives (baseline PTX, sm_80+) ----------------
__device__ __forceinline__ void ldsm4(uint32_t addr, uint32_t* r) {
    asm volatile("ldmatrix.sync.aligned.m8n8.x4.shared.b16 {%0,%1,%2,%3}, [%4];"
                 : "=r"(r[0]), "=r"(r[1]), "=r"(r[2]), "=r"(r[3]) : "r"(addr));
}
__device__ __forceinline__ void mma16816(float* c, const uint32_t* a, uint32_t b0, uint32_t b1) {
    asm volatile("mma.sync.aligned.m16n8k16.row.col.f32.bf16.bf16.f32 "
                 "{%0,%1,%2,%3}, {%4,%5,%6,%7}, {%8,%9}, {%0,%1,%2,%3};"
                 : "+f"(c[0]), "+f"(c[1]), "+f"(c[2]), "+f"(c[3])
                 : "r"(a[0]), "r"(a[1]), "r"(a[2]), "r"(a[3]), "r"(b0), "r"(b1));
}
__device__ __forceinline__ void cp16(uint32_t s, const void* g) {
    asm volatile("cp.async.cg.shared.global [%0], [%1], 16;" :: "r"(s), "l"(g));
}
#define CP_COMMIT() asm volatile("cp.async.commit_group;" ::: "memory")
#define CP_WAIT0()  asm volatile("cp.async.wait_group 0;" ::: "memory")
#define CP_WAIT1()  asm volatile("cp.async.wait_group 1;" ::: "memory")

// SMEM stage: AH@0, AL@10240, BH@20480, BL@30720 (pitch 80B rows), stage 40960, 2 stages
#define PITCH 80
#define STG   40960
#define DSMEM (2*STG)

// 3-term chunk, warp tile 32x64 (R10-proven)
__device__ __forceinline__ void mma_chunk32(uint32_t sb, int wm, int wn,
                                            int arow, int acol, int brow, int bcol,
                                            float c[2][8][4]) {
#pragma unroll
    for (int ks = 0; ks < 32; ks += 16) {
        uint32_t ah0[4], ah1[4], al0[4], al1[4];
        uint32_t aoff = (uint32_t)((wm * 32 + arow) * PITCH + (ks + acol) * 2);
        ldsm4(sb + aoff, ah0);
        ldsm4(sb + aoff + 16 * PITCH, ah1);
        ldsm4(sb + 10240 + aoff, al0);
        ldsm4(sb + 10240 + aoff + 16 * PITCH, al1);
#pragma unroll
        for (int np = 0; np < 4; np++) {
            uint32_t bh[4], bl[4];
            uint32_t boff = (uint32_t)((wn * 64 + np * 16 + brow) * PITCH + (ks + bcol) * 2);
            ldsm4(sb + 20480 + boff, bh);
            ldsm4(sb + 30720 + boff, bl);
            mma16816(c[0][np * 2],     ah0, bh[0], bh[1]);
            mma16816(c[1][np * 2],     ah1, bh[0], bh[1]);
            mma16816(c[0][np * 2 + 1], ah0, bh[2], bh[3]);
            mma16816(c[1][np * 2 + 1], ah1, bh[2], bh[3]);
            mma16816(c[0][np * 2],     al0, bh[0], bh[1]);
            mma16816(c[1][np * 2],     al1, bh[0], bh[1]);
            mma16816(c[0][np * 2 + 1], al0, bh[2], bh[3]);
            mma16816(c[1][np * 2 + 1], al1, bh[2], bh[3]);
            mma16816(c[0][np * 2],     ah0, bl[0], bl[1]);
            mma16816(c[1][np * 2],     ah1, bl[0], bl[1]);
            mma16816(c[0][np * 2 + 1], ah0, bl[2], bl[3]);
            mma16816(c[1][np * 2 + 1], ah1, bl[2], bl[3]);
        }
    }
}

// 1-term chunk (Ah*Bh only) — for low-magnitude attn-feature K range
__device__ __forceinline__ void mma_chunk32_h(uint32_t sb, int wm, int wn,
                                              int arow, int acol, int brow, int bcol,
                                              float c[2][8][4]) {
#pragma unroll
    for (int ks = 0; ks < 32; ks += 16) {
        uint32_t ah0[4], ah1[4];
        uint32_t aoff = (uint32_t)((wm * 32 + arow) * PITCH + (ks + acol) * 2);
        ldsm4(sb + aoff, ah0);
        ldsm4(sb + aoff + 16 * PITCH, ah1);
#pragma unroll
        for (int np = 0; np < 4; np++) {
            uint32_t bh[4];
            uint32_t boff = (uint32_t)((wn * 64 + np * 16 + brow) * PITCH + (ks + bcol) * 2);
            ldsm4(sb + 20480 + boff, bh);
            mma16816(c[0][np * 2],     ah0, bh[0], bh[1]);
            mma16816(c[1][np * 2],     ah1, bh[0], bh[1]);
            mma16816(c[0][np * 2 + 1], ah0, bh[2], bh[3]);
            mma16816(c[1][np * 2 + 1], ah1, bh[2], bh[3]);
        }
    }
}

// ---------------- prep kernels ----------------
__global__ void k_prep_bn(const float* kg, const float* kb, const float* km, const float* kv,
                          const float* qg, const float* qb, const float* qm, const float* qv,
                          const float* pg, const float* pb, const float* pm, const float* pv) {
    int i = blockIdx.x * 256 + threadIdx.x;
    if (i < HKV) {
        float s = kg[i] * rsqrtf(kv[i] + EPSV);
        g_kvs[i] = s; g_kvt[i] = kb[i] - km[i] * s;
    } else if (i < HKV + 128) {
        int j = i - HKV;
        float s = qg[j] * rsqrtf(qv[j] + EPSV);
        g_qsA[j] = s; g_qtA[j] = qb[j] - qm[j] * s;
    } else if (i < HKV + 128 + DIMC) {
        int j = i - HKV - 128;
        float s = pg[j] * rsqrtf(pv[j] + EPSV);
        g_psA[j] = s; g_ptA[j] = pb[j] - pm[j] * s;
    }
}
__global__ void k_split_x(const float* __restrict__ src) {
    int i = blockIdx.x * 256 + threadIdx.x;
    if (i >= MTOT * DIMC / 4) return;
    float4 v = ((const float4*)src)[i];
    unsigned long long H, L; split4(v, H, L);
    ((unsigned long long*)g_xh)[i] = H;
    ((unsigned long long*)g_xl)[i] = L;
}
__global__ void k_split_kw(const float* __restrict__ src) {
    int i = blockIdx.x * 256 + threadIdx.x;
    if (i >= HKV * DIMC / 4) return;
    float4 v = ((const float4*)src)[i];
    unsigned long long H, L; split4(v, H, L);
    ((unsigned long long*)g_kwh)[i] = H;
    ((unsigned long long*)g_kwl)[i] = L;
}
__global__ void k_split_pw(const float* __restrict__ src) {
    int i = blockIdx.x * 256 + threadIdx.x;
    if (i >= DIMC * (KEFF / 4)) return;
    int r = i / (KEFF / 4), c = i % (KEFF / 4);
    float4 v = *(const float4*)(src + (size_t)r * PROJIN + c * 4);
    unsigned long long H, L; split4(v, H, L);
    ((unsigned long long*)g_pwh)[i] = H;
    ((unsigned long long*)g_pwl)[i] = L;
}

// ---------------- kernel: q projection + BN ----------------
__global__ void k_qproj(const float* __restrict__ text, const float* __restrict__ qw) {
    int o = blockIdx.x * blockDim.x + threadIdx.x;
    if (o >= NTOK * 128) return;
    int t = o >> 7, col = o & 127;
    const float4* tr = (const float4*)(text + t * DIMC);
    const float4* wr = (const float4*)(qw + col * DIMC);
    float acc = 0.f;
#pragma unroll 16
    for (int k = 0; k < DIMC / 4; k++) {
        float4 a = tr[k], w = wr[k];
        acc += a.x * w.x + a.y * w.y + a.z * w.z + a.w * w.w;
    }
    g_q[o] = acc * g_qsA[col] + g_qtA[col];
}

// ---------------- kernel: kv GEMM (R10-proven: 256 thr, warp 32x64, 2-stage cp.async) ----------------
__global__ __launch_bounds__(256) void k_kv_mma() {
    extern __shared__ __align__(128) unsigned char sm[];
    uint32_t s0 = smem_u32(sm);
    const int tid = threadIdx.x, lane = tid & 31, wid = tid >> 5;
    const int m0 = blockIdx.y * 128, n0 = blockIdx.x * 128;
    const int wm = wid >> 1, wn = wid & 1;
    const int arow = ((lane >> 3) & 1) * 8 + (lane & 7), acol = (lane >> 4) * 8;
    const int brow = (lane >> 4) * 8 + (lane & 7), bcol = ((lane >> 3) & 1) * 8;
    const __nv_bfloat16* pAH = g_xh + (size_t)m0 * DIMC;
    const __nv_bfloat16* pAL = g_xl + (size_t)m0 * DIMC;
    const __nv_bfloat16* pBH = g_kwh + (size_t)n0 * DIMC;
    const __nv_bfloat16* pBL = g_kwl + (size_t)n0 * DIMC;
    float c[2][8][4] = {};

    auto LOAD = [&](int kc) {
        const int kt = kc * 32;
        const uint32_t sb = s0 + (kc & 1) * STG;
#pragma unroll
        for (int i = 0; i < 8; i++) {
            int item = tid + i * 256;
            int ab = item >> 10, arr = (item >> 9) & 1, row = (item >> 2) & 127, c16 = item & 3;
            const __nv_bfloat16* src = ab ? (arr ? pBL : pBH) : (arr ? pAL : pAH);
            src += (size_t)row * DIMC + kt + c16 * 8;
            cp16(sb + ab * 20480 + arr * 10240 + row * PITCH + c16 * 16, src);
        }
    };

    LOAD(0); CP_COMMIT();
#pragma unroll 1
    for (int kc = 0; kc < 8; kc++) {
        if (kc < 7) { LOAD(kc + 1); CP_COMMIT(); CP_WAIT1(); }
        else        { CP_WAIT0(); }
        __syncthreads();
        mma_chunk32(s0 + (kc & 1) * STG, wm, wn, arow, acol, brow, bcol, c);
        __syncthreads();
    }

    unsigned short* VH = (unsigned short*)g_vh;
    unsigned short* VL = (unsigned short*)g_vl;
#pragma unroll
    for (int mi = 0; mi < 2; mi++) {
        int row = m0 + wm * 32 + mi * 16 + (lane >> 2);
#pragma unroll
        for (int ni = 0; ni < 8; ni++) {
#pragma unroll
            for (int cc = 0; cc < 2; cc++) {
                int col = n0 + wn * 64 + ni * 8 + (lane & 3) * 2 + cc;
                float s = g_kvs[col], t = g_kvt[col];
                int h = col / 80, r = col % 80;
                float y0 = c[mi][ni][cc] * s + t;
                float y1 = c[mi][ni][cc + 2] * s + t;
                if (r < 16) {
                    g_k[(size_t)row * 128 + h * 16 + r] = y0;
                    g_k[(size_t)(row + 8) * 128 + h * 16 + r] = y1;
                } else {
                    unsigned short hu, lu;
                    size_t i0 = (size_t)row * 512 + h * 64 + (r - 16);
                    size_t i1 = (size_t)(row + 8) * 512 + h * 64 + (r - 16);
                    splitbf(hswish(y0), hu, lu); VH[i0] = hu; VL[i0] = lu;
                    splitbf(hswish(y1), hu, lu); VH[i1] = hu; VL[i1] = lu;
                }
            }
        }
    }
}

// ---------------- kernel: attention + softmax + hswish -> SINGLE bf16 (coalesced) ----------------
__global__ __launch_bounds__(1024) void k_attn(const float* __restrict__ biases) {
    const int h = blockIdx.x, b = blockIdx.y;
    const int tid = threadIdx.x;
    __shared__ float qs[NTOK * 16];
    __shared__ float bias_s[3200];
    __shared__ float red[32 * 10];
    __shared__ float bcast[10];

    float kr[16];
    const float4* kp = (const float4*)(g_k + (size_t)(b * NSEQ + tid) * 128 + h * 16);
#pragma unroll
    for (int i = 0; i < 4; i++) {
        float4 v = kp[i];
        kr[i * 4] = v.x; kr[i * 4 + 1] = v.y; kr[i * 4 + 2] = v.z; kr[i * 4 + 3] = v.w;
    }
    for (int i = tid; i < NTOK * 16; i += 1024) qs[i] = g_q[(i >> 4) * 128 + (i & 15) + h * 16];
    for (int i = tid; i < 3200; i += 1024) bias_s[i] = biases[h * 10000 + i];
    __syncthreads();

    const int p2x = tid >> 5, p2y = tid & 31;
    const int warp = tid >> 5, lane = tid & 31;
    __nv_bfloat16* AH = g_ah;
    size_t obase = ((size_t)(b * NHEAD + h) * NTOK) * NSEQ + tid;

    for (int t0 = 0; t0 < NTOK; t0 += 10) {
        float e[10];
#pragma unroll
        for (int cch = 0; cch < 10; cch++) {
            int t = t0 + cch;
            float logit = 0.f;
#pragma unroll
            for (int d = 0; d < 16; d++) logit += qs[t * 16 + d] * kr[d];
            int dy = t - p2y; if (dy < 0) dy = -dy;
            logit = logit * 0.25f + bias_s[p2x * 100 + dy];
            float ex = __expf(logit);
            e[cch] = ex;
            float s = ex;
#pragma unroll
            for (int o = 16; o > 0; o >>= 1) s += __shfl_xor_sync(0xffffffffu, s, o);
            if (lane == 0) red[warp * 10 + cch] = s;
        }
        __syncthreads();
        if (warp == 0) {
#pragma unroll
            for (int cch = 0; cch < 10; cch++) {
                float v = red[lane * 10 + cch];
#pragma unroll
                for (int o = 16; o > 0; o >>= 1) v += __shfl_xor_sync(0xffffffffu, v, o);
                if (lane == 0) bcast[cch] = v;
            }
        }
        __syncthreads();
#pragma unroll
        for (int cch = 0; cch < 10; cch++) {
            float p = e[cch] * __frcp_rn(bcast[cch]);
            float y = p * (p + 3.f) * (1.f / 6.f);
            AH[obase + (size_t)(t0 + cch) * NSEQ] = __float2bfloat16_rn(y);
        }
    }
}

// ---------------- kernel: proj GEMM (R10 geometry; 1-term mma for attn K-range) ----------------
__global__ __launch_bounds__(256) void k_proj_mma(float* __restrict__ out) {
    extern __shared__ __align__(128) unsigned char sm[];
    uint32_t s0 = smem_u32(sm);
    const int tid = threadIdx.x, lane = tid & 31, wid = tid >> 5;
    const int m0 = blockIdx.y * 128, n0 = blockIdx.x * 128;
    const int b = m0 >> 10, nbase = m0 & 1023;
    const int rowbase = b * 800;
    const int wm = wid >> 1, wn = wid & 1;
    const int arow = ((lane >> 3) & 1) * 8 + (lane & 7), acol = (lane >> 4) * 8;
    const int brow = (lane >> 4) * 8 + (lane & 7), bcol = ((lane >> 3) & 1) * 8;
    const __nv_bfloat16* pAH = g_vh + (size_t)m0 * 512;
    const __nv_bfloat16* pAL = g_vl + (size_t)m0 * 512;
    const __nv_bfloat16* pBH = g_pwh + (size_t)n0 * KEFF;
    const __nv_bfloat16* pBL = g_pwl + (size_t)n0 * KEFF;
    const unsigned short* GAH = (const unsigned short*)g_ah;
    float c[2][8][4] = {};

    auto LOAD = [&](int kc) {
        const int kt = kc * 32;
        const uint32_t sb = s0 + (kc & 1) * STG;
        unsigned char* smb = sm + (kc & 1) * STG;
        if (kt < 512) {
            // B hi+lo
#pragma unroll
            for (int i = 0; i < 4; i++) {
                int item = tid + i * 256;
                int arr = item >> 9, row = (item >> 2) & 127, c16 = item & 3;
                const __nv_bfloat16* src = (arr ? pBL : pBH) + (size_t)row * KEFF + kt + c16 * 8;
                cp16(sb + 20480 + arr * 10240 + row * PITCH + c16 * 16, src);
            }
            // A (v) hi+lo
#pragma unroll
            for (int i = 0; i < 4; i++) {
                int item = tid + i * 256;
                int arr = item >> 9, row = (item >> 2) & 127, c16 = item & 3;
                const __nv_bfloat16* src = (arr ? pAL : pAH) + (size_t)row * 512 + kt + c16 * 8;
                cp16(sb + arr * 10240 + row * PITCH + c16 * 16, src);
            }
        } else {
            // B hi only
#pragma unroll
            for (int i = 0; i < 2; i++) {
                int item = tid + i * 256;
                int row = item >> 2, c16 = item & 3;
                const __nv_bfloat16* src = pBH + (size_t)row * KEFF + kt + c16 * 8;
                cp16(sb + 20480 + row * PITCH + c16 * 16, src);
            }
            // A (attn) hi only: coalesced read + 2B transpose into SMEM
            const int kloc = kt - 512;
#pragma unroll
            for (int i = 0; i < 4; i++) {
                int item = tid + i * 256;
                int krow = item >> 5, nn = (item & 31) * 4;
                size_t idx = (size_t)(rowbase + kloc + krow) * NSEQ + nbase + nn;
                unsigned long long vh = *(const unsigned long long*)(GAH + idx);
                *(unsigned short*)(smb + nn * PITCH + krow * 2)       = (unsigned short)vh;
                *(unsigned short*)(smb + (nn + 1) * PITCH + krow * 2) = (unsigned short)(vh >> 16);
                *(unsigned short*)(smb + (nn + 2) * PITCH + krow * 2) = (unsigned short)(vh >> 32);
                *(unsigned short*)(smb + (nn + 3) * PITCH + krow * 2) = (unsigned short)(vh >> 48);
            }
        }
    };

    LOAD(0); CP_COMMIT();
#pragma unroll 1
    for (int kc = 0; kc < 41; kc++) {
        if (kc < 40) { LOAD(kc + 1); CP_COMMIT(); CP_WAIT1(); }
        else         { CP_WAIT0(); }
        __syncthreads();
        if (kc < 16) mma_chunk32  (s0 + (kc & 1) * STG, wm, wn, arow, acol, brow, bcol, c);
        else         mma_chunk32_h(s0 + (kc & 1) * STG, wm, wn, arow, acol, brow, bcol, c);
        __syncthreads();
    }

    // epilogue: BN -> out
#pragma unroll
    for (int mi = 0; mi < 2; mi++) {
        int row = m0 + wm * 32 + mi * 16 + (lane >> 2);
#pragma unroll
        for (int ni = 0; ni < 8; ni++) {
#pragma unroll
            for (int cc = 0; cc < 2; cc++) {
                int col = n0 + wn * 64 + ni * 8 + (lane & 3) * 2 + cc;
                float s = g_psA[col], t = g_ptA[col];
                out[(size_t)row * DIMC + col]       = c[mi][ni][cc] * s + t;
                out[(size_t)(row + 8) * DIMC + col] = c[mi][ni][cc + 2] * s + t;
            }
        }
    }
}

// ---------------- launch ----------------
extern "C" void kernel_launch(void* const* d_in, const int* in_sizes, int n_in,
                              void* d_out, int out_size) {
    const float* x      = (const float*)d_in[0];
    const float* text   = (const float*)d_in[1];
    const float* kv_w   = (const float*)d_in[2];
    const float* kv_g   = (const float*)d_in[3];
    const float* kv_b   = (const float*)d_in[4];
    const float* kv_m   = (const float*)d_in[5];
    const float* kv_v   = (const float*)d_in[6];
    const float* q_w    = (const float*)d_in[7];
    const float* q_g    = (const float*)d_in[8];
    const float* q_b    = (const float*)d_in[9];
    const float* q_m    = (const float*)d_in[10];
    const float* q_v    = (const float*)d_in[11];
    const float* proj_w = (const float*)d_in[12];
    const float* proj_g = (const float*)d_in[13];
    const float* proj_b = (const float*)d_in[14];
    const float* proj_m = (const float*)d_in[15];
    const float* proj_v = (const float*)d_in[16];
    const float* biases = (const float*)d_in[17];
    float* out = (float*)d_out;

    cudaFuncSetAttribute(k_kv_mma,   cudaFuncAttributeMaxDynamicSharedMemorySize, DSMEM);
    cudaFuncSetAttribute(k_proj_mma, cudaFuncAttributeMaxDynamicSharedMemorySize, DSMEM);

    k_prep_bn<<<4, 256>>>(kv_g, kv_b, kv_m, kv_v, q_g, q_b, q_m, q_v,
                          proj_g, proj_b, proj_m, proj_v);
    k_split_x<<<(MTOT * DIMC / 4 + 255) / 256, 256>>>(x);
    k_split_kw<<<(HKV * DIMC / 4 + 255) / 256, 256>>>(kv_w);
    k_split_pw<<<(DIMC * (KEFF / 4) + 255) / 256, 256>>>(proj_w);
    k_qproj<<<50, 256>>>(text, q_w);
    k_kv_mma<<<dim3(HKV / 128, MTOT / 128), 256, DSMEM>>>();
    k_attn<<<dim3(NHEAD, BB), 1024>>>(biases);
    k_proj_mma<<<dim3(2, MTOT / 128), 256, DSMEM>>>(out);
}

// round 13
// speedup vs baseline: 1.2517x; 1.0760x over previous
#include <cuda_runtime.h>
#include <cuda_bf16.h>
#include <cstdint>

// ---------------- problem constants ----------------
#define BB    64
#define NSEQ  1024
#define NTOK  100
#define DIMC  256
#define NHEAD 8
#define HKV   640
#define PROJIN 1512
#define KEFF  1312
#define EPSV  1e-5f
#define MTOT  (BB*NSEQ)

// ---------------- scratch ----------------
__device__ float g_q[NTOK * 128];
__device__ float g_k[(size_t)MTOT * 128];
__device__ __nv_bfloat16 g_xh[(size_t)MTOT * DIMC];
__device__ __nv_bfloat16 g_xl[(size_t)MTOT * DIMC];
__device__ __nv_bfloat16 g_kwh[HKV * DIMC];
__device__ __nv_bfloat16 g_kwl[HKV * DIMC];
__device__ __nv_bfloat16 g_pwh[DIMC * KEFF];
__device__ __nv_bfloat16 g_pwl[DIMC * KEFF];
__device__ __nv_bfloat16 g_vh[(size_t)MTOT * 512];
__device__ __nv_bfloat16 g_vl[(size_t)MTOT * 512];
__device__ __nv_bfloat16 g_ah[(size_t)BB * NHEAD * NTOK * NSEQ];   // hswish(p), bf16, (b,h,t,n)
__device__ float g_kvs[HKV], g_kvt[HKV];
__device__ float g_qsA[128], g_qtA[128];
__device__ float g_psA[DIMC], g_ptA[DIMC];

__device__ __forceinline__ float hswish(float y) {
    return y * fminf(fmaxf(y + 3.f, 0.f), 6.f) * (1.f / 6.f);
}
__device__ __forceinline__ uint32_t smem_u32(const void* p) {
    uint32_t a;
    asm("{ .reg .u64 t; cvta.to.shared.u64 t, %1; cvt.u32.u64 %0, t; }" : "=r"(a) : "l"(p));
    return a;
}
__device__ __forceinline__ void split4(float4 v, unsigned long long& H, unsigned long long& L) {
    float f[4] = {v.x, v.y, v.z, v.w};
    unsigned long long h = 0, l = 0;
#pragma unroll
    for (int i = 0; i < 4; i++) {
        __nv_bfloat16 hb = __float2bfloat16_rn(f[i]);
        float r = f[i] - __bfloat162float(hb);
        __nv_bfloat16 lb = __float2bfloat16_rn(r);
        h |= (unsigned long long)__bfloat16_as_ushort(hb) << (16 * i);
        l |= (unsigned long long)__bfloat16_as_ushort(lb) << (16 * i);
    }
    H = h; L = l;
}
__device__ __forceinline__ void splitbf(float y, unsigned short& hu, unsigned short& lu) {
    __nv_bfloat16 hb = __float2bfloat16_rn(y);
    float r = y - __bfloat162float(hb);
    __nv_bfloat16 lb = __float2bfloat16_rn(r);
    hu = __bfloat16_as_ushort(hb); lu = __bfloat16_as_ushort(lb);
}

// ---------------- warp-mma + cp.async primitives ----------------
__device__ __forceinline__ void ldsm4(uint32_t addr, uint32_t* r) {
    asm volatile("ldmatrix.sync.aligned.m8n8.x4.shared.b16 {%0,%1,%2,%3}, [%4];"
                 : "=r"(r[0]), "=r"(r[1]), "=r"(r[2]), "=r"(r[3]) : "r"(addr));
}
__device__ __forceinline__ void mma16816(float* c, const uint32_t* a, uint32_t b0, uint32_t b1) {
    asm volatile("mma.sync.aligned.m16n8k16.row.col.f32.bf16.bf16.f32 "
                 "{%0,%1,%2,%3}, {%4,%5,%6,%7}, {%8,%9}, {%0,%1,%2,%3};"
                 : "+f"(c[0]), "+f"(c[1]), "+f"(c[2]), "+f"(c[3])
                 : "r"(a[0]), "r"(a[1]), "r"(a[2]), "r"(a[3]), "r"(b0), "r"(b1));
}
__device__ __forceinline__ void cp16(uint32_t s, const void* g) {
    asm volatile("cp.async.cg.shared.global [%0], [%1], 16;" :: "r"(s), "l"(g));
}
#define CP_COMMIT() asm volatile("cp.async.commit_group;" ::: "memory")
#define CP_WAIT0()  asm volatile("cp.async.wait_group 0;" ::: "memory")
#define CP_WAIT1()  asm volatile("cp.async.wait_group 1;" ::: "memory")

// Swizzled tile: pitch 64B, 16B-chunk XOR (row>>1)&3. Tiles: AH@0, AL@8192, BH@16384, BL@24576.
// Stage 32768, 3 stages.
#define STG   32768
#define DSMEM (3*STG)
// byte offset of (row, chunk16) in a tile
__device__ __forceinline__ uint32_t swz(int row, int c16) {
    return (uint32_t)(row * 64 + ((c16 ^ ((row >> 1) & 3)) << 4));
}

// 3-term chunk, warp tile 32x64; addressing identical to R12 modulo swizzled layout
__device__ __forceinline__ void mma_chunk32(uint32_t sb, int wm, int wn,
                                            int arow, int acol, int brow, int bcol,
                                            float c[2][8][4]) {
#pragma unroll
    for (int ks = 0; ks < 32; ks += 16) {
        uint32_t ah0[4], ah1[4], al0[4], al1[4];
        int ar0 = wm * 32 + arow;
        int ac = (ks + acol) >> 3;           // 16B-chunk index 0..3
        ldsm4(sb + swz(ar0, ac), ah0);
        ldsm4(sb + swz(ar0 + 16, ac), ah1);
        ldsm4(sb + 8192 + swz(ar0, ac), al0);
        ldsm4(sb + 8192 + swz(ar0 + 16, ac), al1);
#pragma unroll
        for (int np = 0; np < 4; np++) {
            uint32_t bh[4], bl[4];
            int br = wn * 64 + np * 16 + brow;
            int bc = (ks + bcol) >> 3;
            ldsm4(sb + 16384 + swz(br, bc), bh);
            ldsm4(sb + 24576 + swz(br, bc), bl);
            mma16816(c[0][np * 2],     ah0, bh[0], bh[1]);
            mma16816(c[1][np * 2],     ah1, bh[0], bh[1]);
            mma16816(c[0][np * 2 + 1], ah0, bh[2], bh[3]);
            mma16816(c[1][np * 2 + 1], ah1, bh[2], bh[3]);
            mma16816(c[0][np * 2],     al0, bh[0], bh[1]);
            mma16816(c[1][np * 2],     al1, bh[0], bh[1]);
            mma16816(c[0][np * 2 + 1], al0, bh[2], bh[3]);
            mma16816(c[1][np * 2 + 1], al1, bh[2], bh[3]);
            mma16816(c[0][np * 2],     ah0, bl[0], bl[1]);
            mma16816(c[1][np * 2],     ah1, bl[0], bl[1]);
            mma16816(c[0][np * 2 + 1], ah0, bl[2], bl[3]);
            mma16816(c[1][np * 2 + 1], ah1, bl[2], bl[3]);
        }
    }
}

// 1-term chunk (Ah*Bh only)
__device__ __forceinline__ void mma_chunk32_h(uint32_t sb, int wm, int wn,
                                              int arow, int acol, int brow, int bcol,
                                              float c[2][8][4]) {
#pragma unroll
    for (int ks = 0; ks < 32; ks += 16) {
        uint32_t ah0[4], ah1[4];
        int ar0 = wm * 32 + arow;
        int ac = (ks + acol) >> 3;
        ldsm4(sb + swz(ar0, ac), ah0);
        ldsm4(sb + swz(ar0 + 16, ac), ah1);
#pragma unroll
        for (int np = 0; np < 4; np++) {
            uint32_t bh[4];
            int br = wn * 64 + np * 16 + brow;
            int bc = (ks + bcol) >> 3;
            ldsm4(sb + 16384 + swz(br, bc), bh);
            mma16816(c[0][np * 2],     ah0, bh[0], bh[1]);
            mma16816(c[1][np * 2],     ah1, bh[0], bh[1]);
            mma16816(c[0][np * 2 + 1], ah0, bh[2], bh[3]);
            mma16816(c[1][np * 2 + 1], ah1, bh[2], bh[3]);
        }
    }
}

// ---------------- prep kernels ----------------
__global__ void k_prep_bn(const float* kg, const float* kb, const float* km, const float* kv,
                          const float* qg, const float* qb, const float* qm, const float* qv,
                          const float* pg, const float* pb, const float* pm, const float* pv) {
    int i = blockIdx.x * 256 + threadIdx.x;
    if (i < HKV) {
        float s = kg[i] * rsqrtf(kv[i] + EPSV);
        g_kvs[i] = s; g_kvt[i] = kb[i] - km[i] * s;
    } else if (i < HKV + 128) {
        int j = i - HKV;
        float s = qg[j] * rsqrtf(qv[j] + EPSV);
        g_qsA[j] = s; g_qtA[j] = qb[j] - qm[j] * s;
    } else if (i < HKV + 128 + DIMC) {
        int j = i - HKV - 128;
        float s = pg[j] * rsqrtf(pv[j] + EPSV);
        g_psA[j] = s; g_ptA[j] = pb[j] - pm[j] * s;
    }
}
__global__ void k_split_x(const float* __restrict__ src) {
    int i = blockIdx.x * 256 + threadIdx.x;
    if (i >= MTOT * DIMC / 4) return;
    float4 v = ((const float4*)src)[i];
    unsigned long long H, L; split4(v, H, L);
    ((unsigned long long*)g_xh)[i] = H;
    ((unsigned long long*)g_xl)[i] = L;
}
__global__ void k_split_kw(const float* __restrict__ src) {
    int i = blockIdx.x * 256 + threadIdx.x;
    if (i >= HKV * DIMC / 4) return;
    float4 v = ((const float4*)src)[i];
    unsigned long long H, L; split4(v, H, L);
    ((unsigned long long*)g_kwh)[i] = H;
    ((unsigned long long*)g_kwl)[i] = L;
}
__global__ void k_split_pw(const float* __restrict__ src) {
    int i = blockIdx.x * 256 + threadIdx.x;
    if (i >= DIMC * (KEFF / 4)) return;
    int r = i / (KEFF / 4), c = i % (KEFF / 4);
    float4 v = *(const float4*)(src + (size_t)r * PROJIN + c * 4);
    unsigned long long H, L; split4(v, H, L);
    ((unsigned long long*)g_pwh)[i] = H;
    ((unsigned long long*)g_pwl)[i] = L;
}

// ---------------- kernel: q projection + BN ----------------
__global__ void k_qproj(const float* __restrict__ text, const float* __restrict__ qw) {
    int o = blockIdx.x * blockDim.x + threadIdx.x;
    if (o >= NTOK * 128) return;
    int t = o >> 7, col = o & 127;
    const float4* tr = (const float4*)(text + t * DIMC);
    const float4* wr = (const float4*)(qw + col * DIMC);
    float acc = 0.f;
#pragma unroll 16
    for (int k = 0; k < DIMC / 4; k++) {
        float4 a = tr[k], w = wr[k];
        acc += a.x * w.x + a.y * w.y + a.z * w.z + a.w * w.w;
    }
    g_q[o] = acc * g_qsA[col] + g_qtA[col];
}

// ---------------- kernel: kv GEMM (3-stage, single sync per chunk, swizzled tiles) ----------------
__global__ __launch_bounds__(256) void k_kv_mma() {
    extern __shared__ __align__(128) unsigned char sm[];
    uint32_t s0 = smem_u32(sm);
    const int tid = threadIdx.x, lane = tid & 31, wid = tid >> 5;
    const int m0 = blockIdx.y * 128, n0 = blockIdx.x * 128;
    const int wm = wid >> 1, wn = wid & 1;
    const int arow = ((lane >> 3) & 1) * 8 + (lane & 7), acol = (lane >> 4) * 8;
    const int brow = (lane >> 4) * 8 + (lane & 7), bcol = ((lane >> 3) & 1) * 8;
    const __nv_bfloat16* pAH = g_xh + (size_t)m0 * DIMC;
    const __nv_bfloat16* pAL = g_xl + (size_t)m0 * DIMC;
    const __nv_bfloat16* pBH = g_kwh + (size_t)n0 * DIMC;
    const __nv_bfloat16* pBL = g_kwl + (size_t)n0 * DIMC;
    float c[2][8][4] = {};

    auto LOAD = [&](int kc) {
        const int kt = kc * 32;
        const uint32_t sb = s0 + (kc % 3) * STG;
#pragma unroll
        for (int i = 0; i < 8; i++) {
            int item = tid + i * 256;
            int ab = item >> 10, arr = (item >> 9) & 1, row = (item >> 2) & 127, c16 = item & 3;
            const __nv_bfloat16* src = ab ? (arr ? pBL : pBH) : (arr ? pAL : pAH);
            src += (size_t)row * DIMC + kt + c16 * 8;
            cp16(sb + ab * 16384 + arr * 8192 + swz(row, c16), src);
        }
    };

    LOAD(0); CP_COMMIT();
    LOAD(1); CP_COMMIT();
#pragma unroll 1
    for (int kc = 0; kc < 8; kc++) {
        if (kc < 7) { CP_WAIT1(); } else { CP_WAIT0(); }
        __syncthreads();
        mma_chunk32(s0 + (kc % 3) * STG, wm, wn, arow, acol, brow, bcol, c);
        if (kc + 2 < 8) { LOAD(kc + 2); CP_COMMIT(); }
    }

    unsigned short* VH = (unsigned short*)g_vh;
    unsigned short* VL = (unsigned short*)g_vl;
#pragma unroll
    for (int mi = 0; mi < 2; mi++) {
        int row = m0 + wm * 32 + mi * 16 + (lane >> 2);
#pragma unroll
        for (int ni = 0; ni < 8; ni++) {
#pragma unroll
            for (int cc = 0; cc < 2; cc++) {
                int col = n0 + wn * 64 + ni * 8 + (lane & 3) * 2 + cc;
                float s = g_kvs[col], t = g_kvt[col];
                int h = col / 80, r = col % 80;
                float y0 = c[mi][ni][cc] * s + t;
                float y1 = c[mi][ni][cc + 2] * s + t;
                if (r < 16) {
                    g_k[(size_t)row * 128 + h * 16 + r] = y0;
                    g_k[(size_t)(row + 8) * 128 + h * 16 + r] = y1;
                } else {
                    unsigned short hu, lu;
                    size_t i0 = (size_t)row * 512 + h * 64 + (r - 16);
                    size_t i1 = (size_t)(row + 8) * 512 + h * 64 + (r - 16);
                    splitbf(hswish(y0), hu, lu); VH[i0] = hu; VL[i0] = lu;
                    splitbf(hswish(y1), hu, lu); VH[i1] = hu; VL[i1] = lu;
                }
            }
        }
    }
}

// ---------------- kernel: attention + softmax + hswish -> bf16 (coalesced) ----------------
__global__ __launch_bounds__(1024) void k_attn(const float* __restrict__ biases) {
    const int h = blockIdx.x, b = blockIdx.y;
    const int tid = threadIdx.x;
    __shared__ float qs[NTOK * 16];
    __shared__ float bias_s[3200];
    __shared__ float red[32 * 10];
    __shared__ float bcast[10];

    float kr[16];
    const float4* kp = (const float4*)(g_k + (size_t)(b * NSEQ + tid) * 128 + h * 16);
#pragma unroll
    for (int i = 0; i < 4; i++) {
        float4 v = kp[i];
        kr[i * 4] = v.x; kr[i * 4 + 1] = v.y; kr[i * 4 + 2] = v.z; kr[i * 4 + 3] = v.w;
    }
    for (int i = tid; i < NTOK * 16; i += 1024) qs[i] = g_q[(i >> 4) * 128 + (i & 15) + h * 16];
    for (int i = tid; i < 3200; i += 1024) bias_s[i] = biases[h * 10000 + i];
    __syncthreads();

    const int p2x = tid >> 5, p2y = tid & 31;
    const int warp = tid >> 5, lane = tid & 31;
    __nv_bfloat16* AH = g_ah;
    size_t obase = ((size_t)(b * NHEAD + h) * NTOK) * NSEQ + tid;

    for (int t0 = 0; t0 < NTOK; t0 += 10) {
        float e[10];
#pragma unroll
        for (int cch = 0; cch < 10; cch++) {
            int t = t0 + cch;
            float logit = 0.f;
#pragma unroll
            for (int d = 0; d < 16; d++) logit += qs[t * 16 + d] * kr[d];
            int dy = t - p2y; if (dy < 0) dy = -dy;
            logit = logit * 0.25f + bias_s[p2x * 100 + dy];
            float ex = __expf(logit);
            e[cch] = ex;
            float s = ex;
#pragma unroll
            for (int o = 16; o > 0; o >>= 1) s += __shfl_xor_sync(0xffffffffu, s, o);
            if (lane == 0) red[warp * 10 + cch] = s;
        }
        __syncthreads();
        if (warp == 0) {
#pragma unroll
            for (int cch = 0; cch < 10; cch++) {
                float v = red[lane * 10 + cch];
#pragma unroll
                for (int o = 16; o > 0; o >>= 1) v += __shfl_xor_sync(0xffffffffu, v, o);
                if (lane == 0) bcast[cch] = v;
            }
        }
        __syncthreads();
#pragma unroll
        for (int cch = 0; cch < 10; cch++) {
            float p = e[cch] * __frcp_rn(bcast[cch]);
            float y = p * (p + 3.f) * (1.f / 6.f);
            AH[obase + (size_t)(t0 + cch) * NSEQ] = __float2bfloat16_rn(y);
        }
    }
}

// ---------------- kernel: proj GEMM (3-stage, single sync, swizzled; 1-term attn K-range) ----------------
__global__ __launch_bounds__(256) void k_proj_mma(float* __restrict__ out) {
    extern __shared__ __align__(128) unsigned char sm[];
    uint32_t s0 = smem_u32(sm);
    const int tid = threadIdx.x, lane = tid & 31, wid = tid >> 5;
    const int m0 = blockIdx.y * 128, n0 = blockIdx.x * 128;
    const int b = m0 >> 10, nbase = m0 & 1023;
    const int rowbase = b * 800;
    const int wm = wid >> 1, wn = wid & 1;
    const int arow = ((lane >> 3) & 1) * 8 + (lane & 7), acol = (lane >> 4) * 8;
    const int brow = (lane >> 4) * 8 + (lane & 7), bcol = ((lane >> 3) & 1) * 8;
    const __nv_bfloat16* pAH = g_vh + (size_t)m0 * 512;
    const __nv_bfloat16* pAL = g_vl + (size_t)m0 * 512;
    const __nv_bfloat16* pBH = g_pwh + (size_t)n0 * KEFF;
    const __nv_bfloat16* pBL = g_pwl + (size_t)n0 * KEFF;
    const unsigned short* GAH = (const unsigned short*)g_ah;
    float c[2][8][4] = {};

    auto LOAD = [&](int kc) {
        const int kt = kc * 32;
        const uint32_t sb = s0 + (kc % 3) * STG;
        unsigned char* smb = sm + (kc % 3) * STG;
        if (kt < 512) {
            // B hi+lo
#pragma unroll
            for (int i = 0; i < 4; i++) {
                int item = tid + i * 256;
                int arr = item >> 9, row = (item >> 2) & 127, c16 = item & 3;
                const __nv_bfloat16* src = (arr ? pBL : pBH) + (size_t)row * KEFF + kt + c16 * 8;
                cp16(sb + 16384 + arr * 8192 + swz(row, c16), src);
            }
            // A (v) hi+lo
#pragma unroll
            for (int i = 0; i < 4; i++) {
                int item = tid + i * 256;
                int arr = item >> 9, row = (item >> 2) & 127, c16 = item & 3;
                const __nv_bfloat16* src = (arr ? pAL : pAH) + (size_t)row * 512 + kt + c16 * 8;
                cp16(sb + arr * 8192 + swz(row, c16), src);
            }
        } else {
            // B hi only
#pragma unroll
            for (int i = 0; i < 2; i++) {
                int item = tid + i * 256;
                int row = item >> 2, c16 = item & 3;
                const __nv_bfloat16* src = pBH + (size_t)row * KEFF + kt + c16 * 8;
                cp16(sb + 16384 + swz(row, c16), src);
            }
            // A (attn) hi only: coalesced read + 2B transpose into swizzled tile
            const int kloc = kt - 512;
#pragma unroll
            for (int i = 0; i < 4; i++) {
                int item = tid + i * 256;
                int krow = item >> 5, nn = (item & 31) * 4;
                size_t idx = (size_t)(rowbase + kloc + krow) * NSEQ + nbase + nn;
                unsigned long long vh = *(const unsigned long long*)(GAH + idx);
                int kchunk = krow >> 3, kin = (krow & 7) * 2;
#pragma unroll
                for (int j = 0; j < 4; j++) {
                    *(unsigned short*)(smb + swz(nn + j, kchunk) + kin) =
                        (unsigned short)(vh >> (16 * j));
                }
            }
        }
    };

    LOAD(0); CP_COMMIT();
    LOAD(1); CP_COMMIT();
#pragma unroll 1
    for (int kc = 0; kc < 41; kc++) {
        if (kc < 40) { CP_WAIT1(); } else { CP_WAIT0(); }
        __syncthreads();
        if (kc < 16) mma_chunk32  (s0 + (kc % 3) * STG, wm, wn, arow, acol, brow, bcol, c);
        else         mma_chunk32_h(s0 + (kc % 3) * STG, wm, wn, arow, acol, brow, bcol, c);
        if (kc + 2 < 41) { LOAD(kc + 2); CP_COMMIT(); }
    }

    // epilogue: BN -> out
#pragma unroll
    for (int mi = 0; mi < 2; mi++) {
        int row = m0 + wm * 32 + mi * 16 + (lane >> 2);
#pragma unroll
        for (int ni = 0; ni < 8; ni++) {
#pragma unroll
            for (int cc = 0; cc < 2; cc++) {
                int col = n0 + wn * 64 + ni * 8 + (lane & 3) * 2 + cc;
                float s = g_psA[col], t = g_ptA[col];
                out[(size_t)row * DIMC + col]       = c[mi][ni][cc] * s + t;
                out[(size_t)(row + 8) * DIMC + col] = c[mi][ni][cc + 2] * s + t;
            }
        }
    }
}

// ---------------- launch ----------------
extern "C" void kernel_launch(void* const* d_in, const int* in_sizes, int n_in,
                              void* d_out, int out_size) {
    const float* x      = (const float*)d_in[0];
    const float* text   = (const float*)d_in[1];
    const float* kv_w   = (const float*)d_in[2];
    const float* kv_g   = (const float*)d_in[3];
    const float* kv_b   = (const float*)d_in[4];
    const float* kv_m   = (const float*)d_in[5];
    const float* kv_v   = (const float*)d_in[6];
    const float* q_w    = (const float*)d_in[7];
    const float* q_g    = (const float*)d_in[8];
    const float* q_b    = (const float*)d_in[9];
    const float* q_m    = (const float*)d_in[10];
    const float* q_v    = (const float*)d_in[11];
    const float* proj_w = (const float*)d_in[12];
    const float* proj_g = (const float*)d_in[13];
    const float* proj_b = (const float*)d_in[14];
    const float* proj_m = (const float*)d_in[15];
    const float* proj_v = (const float*)d_in[16];
    const float* biases = (const float*)d_in[17];
    float* out = (float*)d_out;

    cudaFuncSetAttribute(k_kv_mma,   cudaFuncAttributeMaxDynamicSharedMemorySize, DSMEM);
    cudaFuncSetAttribute(k_proj_mma, cudaFuncAttributeMaxDynamicSharedMemorySize, DSMEM);

    k_prep_bn<<<4, 256>>>(kv_g, kv_b, kv_m, kv_v, q_g, q_b, q_m, q_v,
                          proj_g, proj_b, proj_m, proj_v);
    k_split_x<<<(MTOT * DIMC / 4 + 255) / 256, 256>>>(x);
    k_split_kw<<<(HKV * DIMC / 4 + 255) / 256, 256>>>(kv_w);
    k_split_pw<<<(DIMC * (KEFF / 4) + 255) / 256, 256>>>(proj_w);
    k_qproj<<<50, 256>>>(text, q_w);
    k_kv_mma<<<dim3(HKV / 128, MTOT / 128), 256, DSMEM>>>();
    k_attn<<<dim3(NHEAD, BB), 1024>>>(biases);
    k_proj_mma<<<dim3(2, MTOT / 128), 256, DSMEM>>>(out);
}

// round 14
// speedup vs baseline: 1.2602x; 1.0068x over previous
#include <cuda_runtime.h>
#include <cuda_bf16.h>
#include <cstdint>

// ---------------- problem constants ----------------
#define BB    64
#define NSEQ  1024
#define NTOK  100
#define DIMC  256
#define NHEAD 8
#define HKV   640
#define PROJIN 1512
#define KEFF  1312
#define EPSV  1e-5f
#define MTOT  (BB*NSEQ)

// ---------------- scratch ----------------
__device__ float g_q[NTOK * 128];
__device__ float g_k[(size_t)MTOT * 128];
__device__ __nv_bfloat16 g_xh[(size_t)MTOT * DIMC];
__device__ __nv_bfloat16 g_xl[(size_t)MTOT * DIMC];
__device__ __nv_bfloat16 g_kwh[HKV * DIMC];
__device__ __nv_bfloat16 g_kwl[HKV * DIMC];
__device__ __nv_bfloat16 g_pwh[DIMC * KEFF];
__device__ __nv_bfloat16 g_pwl[DIMC * KEFF];
__device__ __nv_bfloat16 g_vh[(size_t)MTOT * 512];
__device__ __nv_bfloat16 g_vl[(size_t)MTOT * 512];
__device__ __nv_bfloat16 g_ah[(size_t)BB * NHEAD * NTOK * NSEQ];   // hswish(p), bf16, (b,h,t,n)
__device__ float g_kvs[HKV], g_kvt[HKV];
__device__ float g_qsA[128], g_qtA[128];
__device__ float g_psA[DIMC], g_ptA[DIMC];

__device__ __forceinline__ float hswish(float y) {
    return y * fminf(fmaxf(y + 3.f, 0.f), 6.f) * (1.f / 6.f);
}
__device__ __forceinline__ uint32_t smem_u32(const void* p) {
    uint32_t a;
    asm("{ .reg .u64 t; cvta.to.shared.u64 t, %1; cvt.u32.u64 %0, t; }" : "=r"(a) : "l"(p));
    return a;
}
__device__ __forceinline__ void split4(float4 v, unsigned long long& H, unsigned long long& L) {
    float f[4] = {v.x, v.y, v.z, v.w};
    unsigned long long h = 0, l = 0;
#pragma unroll
    for (int i = 0; i < 4; i++) {
        __nv_bfloat16 hb = __float2bfloat16_rn(f[i]);
        float r = f[i] - __bfloat162float(hb);
        __nv_bfloat16 lb = __float2bfloat16_rn(r);
        h |= (unsigned long long)__bfloat16_as_ushort(hb) << (16 * i);
        l |= (unsigned long long)__bfloat16_as_ushort(lb) << (16 * i);
    }
    H = h; L = l;
}
__device__ __forceinline__ void splitbf(float y, unsigned short& hu, unsigned short& lu) {
    __nv_bfloat16 hb = __float2bfloat16_rn(y);
    float r = y - __bfloat162float(hb);
    __nv_bfloat16 lb = __float2bfloat16_rn(r);
    hu = __bfloat16_as_ushort(hb); lu = __bfloat16_as_ushort(lb);
}

// ---------------- warp-mma + cp.async primitives ----------------
__device__ __forceinline__ void ldsm4(uint32_t addr, uint32_t* r) {
    asm volatile("ldmatrix.sync.aligned.m8n8.x4.shared.b16 {%0,%1,%2,%3}, [%4];"
                 : "=r"(r[0]), "=r"(r[1]), "=r"(r[2]), "=r"(r[3]) : "r"(addr));
}
__device__ __forceinline__ void mma16816(float* c, const uint32_t* a, uint32_t b0, uint32_t b1) {
    asm volatile("mma.sync.aligned.m16n8k16.row.col.f32.bf16.bf16.f32 "
                 "{%0,%1,%2,%3}, {%4,%5,%6,%7}, {%8,%9}, {%0,%1,%2,%3};"
                 : "+f"(c[0]), "+f"(c[1]), "+f"(c[2]), "+f"(c[3])
                 : "r"(a[0]), "r"(a[1]), "r"(a[2]), "r"(a[3]), "r"(b0), "r"(b1));
}
__device__ __forceinline__ void cp16(uint32_t s, const void* g) {
    asm volatile("cp.async.cg.shared.global [%0], [%1], 16;" :: "r"(s), "l"(g));
}
#define CP_COMMIT() asm volatile("cp.async.commit_group;" ::: "memory")
#define CP_WAIT0()  asm volatile("cp.async.wait_group 0;" ::: "memory")
#define CP_WAIT1()  asm volatile("cp.async.wait_group 1;" ::: "memory")

// Swizzled tile: pitch 64B, 16B-chunk XOR (row>>1)&3. Tiles: AH@0, AL@8192, BH@16384, BL@24576.
// Stage 32768, 3 stages.
#define STG   32768
#define DSMEM (3*STG)
// byte offset of (row, chunk16) in a tile
__device__ __forceinline__ uint32_t swz(int row, int c16) {
    return (uint32_t)(row * 64 + ((c16 ^ ((row >> 1) & 3)) << 4));
}

// 3-term chunk, warp tile 32x64; addressing identical to R12 modulo swizzled layout
__device__ __forceinline__ void mma_chunk32(uint32_t sb, int wm, int wn,
                                            int arow, int acol, int brow, int bcol,
                                            float c[2][8][4]) {
#pragma unroll
    for (int ks = 0; ks < 32; ks += 16) {
        uint32_t ah0[4], ah1[4], al0[4], al1[4];
        int ar0 = wm * 32 + arow;
        int ac = (ks + acol) >> 3;           // 16B-chunk index 0..3
        ldsm4(sb + swz(ar0, ac), ah0);
        ldsm4(sb + swz(ar0 + 16, ac), ah1);
        ldsm4(sb + 8192 + swz(ar0, ac), al0);
        ldsm4(sb + 8192 + swz(ar0 + 16, ac), al1);
#pragma unroll
        for (int np = 0; np < 4; np++) {
            uint32_t bh[4], bl[4];
            int br = wn * 64 + np * 16 + brow;
            int bc = (ks + bcol) >> 3;
            ldsm4(sb + 16384 + swz(br, bc), bh);
            ldsm4(sb + 24576 + swz(br, bc), bl);
            mma16816(c[0][np * 2],     ah0, bh[0], bh[1]);
            mma16816(c[1][np * 2],     ah1, bh[0], bh[1]);
            mma16816(c[0][np * 2 + 1], ah0, bh[2], bh[3]);
            mma16816(c[1][np * 2 + 1], ah1, bh[2], bh[3]);
            mma16816(c[0][np * 2],     al0, bh[0], bh[1]);
            mma16816(c[1][np * 2],     al1, bh[0], bh[1]);
            mma16816(c[0][np * 2 + 1], al0, bh[2], bh[3]);
            mma16816(c[1][np * 2 + 1], al1, bh[2], bh[3]);
            mma16816(c[0][np * 2],     ah0, bl[0], bl[1]);
            mma16816(c[1][np * 2],     ah1, bl[0], bl[1]);
            mma16816(c[0][np * 2 + 1], ah0, bl[2], bl[3]);
            mma16816(c[1][np * 2 + 1], ah1, bl[2], bl[3]);
        }
    }
}

// 1-term chunk (Ah*Bh only)
__device__ __forceinline__ void mma_chunk32_h(uint32_t sb, int wm, int wn,
                                              int arow, int acol, int brow, int bcol,
                                              float c[2][8][4]) {
#pragma unroll
    for (int ks = 0; ks < 32; ks += 16) {
        uint32_t ah0[4], ah1[4];
        int ar0 = wm * 32 + arow;
        int ac = (ks + acol) >> 3;
        ldsm4(sb + swz(ar0, ac), ah0);
        ldsm4(sb + swz(ar0 + 16, ac), ah1);
#pragma unroll
        for (int np = 0; np < 4; np++) {
            uint32_t bh[4];
            int br = wn * 64 + np * 16 + brow;
            int bc = (ks + bcol) >> 3;
            ldsm4(sb + 16384 + swz(br, bc), bh);
            mma16816(c[0][np * 2],     ah0, bh[0], bh[1]);
            mma16816(c[1][np * 2],     ah1, bh[0], bh[1]);
            mma16816(c[0][np * 2 + 1], ah0, bh[2], bh[3]);
            mma16816(c[1][np * 2 + 1], ah1, bh[2], bh[3]);
        }
    }
}

// ---------------- prep kernels ----------------
__global__ void k_prep_bn(const float* kg, const float* kb, const float* km, const float* kv,
                          const float* qg, const float* qb, const float* qm, const float* qv,
                          const float* pg, const float* pb, const float* pm, const float* pv) {
    int i = blockIdx.x * 256 + threadIdx.x;
    if (i < HKV) {
        float s = kg[i] * rsqrtf(kv[i] + EPSV);
        g_kvs[i] = s; g_kvt[i] = kb[i] - km[i] * s;
    } else if (i < HKV + 128) {
        int j = i - HKV;
        float s = qg[j] * rsqrtf(qv[j] + EPSV);
        g_qsA[j] = s; g_qtA[j] = qb[j] - qm[j] * s;
    } else if (i < HKV + 128 + DIMC) {
        int j = i - HKV - 128;
        float s = pg[j] * rsqrtf(pv[j] + EPSV);
        g_psA[j] = s; g_ptA[j] = pb[j] - pm[j] * s;
    }
}
__global__ void k_split_x(const float* __restrict__ src) {
    int i = blockIdx.x * 256 + threadIdx.x;
    if (i >= MTOT * DIMC / 4) return;
    float4 v = ((const float4*)src)[i];
    unsigned long long H, L; split4(v, H, L);
    ((unsigned long long*)g_xh)[i] = H;
    ((unsigned long long*)g_xl)[i] = L;
}
__global__ void k_split_kw(const float* __restrict__ src) {
    int i = blockIdx.x * 256 + threadIdx.x;
    if (i >= HKV * DIMC / 4) return;
    float4 v = ((const float4*)src)[i];
    unsigned long long H, L; split4(v, H, L);
    ((unsigned long long*)g_kwh)[i] = H;
    ((unsigned long long*)g_kwl)[i] = L;
}
__global__ void k_split_pw(const float* __restrict__ src) {
    int i = blockIdx.x * 256 + threadIdx.x;
    if (i >= DIMC * (KEFF / 4)) return;
    int r = i / (KEFF / 4), c = i % (KEFF / 4);
    float4 v = *(const float4*)(src + (size_t)r * PROJIN + c * 4);
    unsigned long long H, L; split4(v, H, L);
    ((unsigned long long*)g_pwh)[i] = H;
    ((unsigned long long*)g_pwl)[i] = L;
}

// ---------------- kernel: q projection + BN ----------------
__global__ void k_qproj(const float* __restrict__ text, const float* __restrict__ qw) {
    int o = blockIdx.x * blockDim.x + threadIdx.x;
    if (o >= NTOK * 128) return;
    int t = o >> 7, col = o & 127;
    const float4* tr = (const float4*)(text + t * DIMC);
    const float4* wr = (const float4*)(qw + col * DIMC);
    float acc = 0.f;
#pragma unroll 16
    for (int k = 0; k < DIMC / 4; k++) {
        float4 a = tr[k], w = wr[k];
        acc += a.x * w.x + a.y * w.y + a.z * w.z + a.w * w.w;
    }
    g_q[o] = acc * g_qsA[col] + g_qtA[col];
}

// ---------------- kernel: kv GEMM (3-stage, single sync per chunk, swizzled tiles) ----------------
__global__ __launch_bounds__(256) void k_kv_mma() {
    extern __shared__ __align__(128) unsigned char sm[];
    uint32_t s0 = smem_u32(sm);
    const int tid = threadIdx.x, lane = tid & 31, wid = tid >> 5;
    const int m0 = blockIdx.y * 128, n0 = blockIdx.x * 128;
    const int wm = wid >> 1, wn = wid & 1;
    const int arow = ((lane >> 3) & 1) * 8 + (lane & 7), acol = (lane >> 4) * 8;
    const int brow = (lane >> 4) * 8 + (lane & 7), bcol = ((lane >> 3) & 1) * 8;
    const __nv_bfloat16* pAH = g_xh + (size_t)m0 * DIMC;
    const __nv_bfloat16* pAL = g_xl + (size_t)m0 * DIMC;
    const __nv_bfloat16* pBH = g_kwh + (size_t)n0 * DIMC;
    const __nv_bfloat16* pBL = g_kwl + (size_t)n0 * DIMC;
    float c[2][8][4] = {};

    auto LOAD = [&](int kc) {
        const int kt = kc * 32;
        const uint32_t sb = s0 + (kc % 3) * STG;
#pragma unroll
        for (int i = 0; i < 8; i++) {
            int item = tid + i * 256;
            int ab = item >> 10, arr = (item >> 9) & 1, row = (item >> 2) & 127, c16 = item & 3;
            const __nv_bfloat16* src = ab ? (arr ? pBL : pBH) : (arr ? pAL : pAH);
            src += (size_t)row * DIMC + kt + c16 * 8;
            cp16(sb + ab * 16384 + arr * 8192 + swz(row, c16), src);
        }
    };

    LOAD(0); CP_COMMIT();
    LOAD(1); CP_COMMIT();
#pragma unroll 1
    for (int kc = 0; kc < 8; kc++) {
        if (kc < 7) { CP_WAIT1(); } else { CP_WAIT0(); }
        __syncthreads();
        mma_chunk32(s0 + (kc % 3) * STG, wm, wn, arow, acol, brow, bcol, c);
        if (kc + 2 < 8) { LOAD(kc + 2); CP_COMMIT(); }
    }

    unsigned short* VH = (unsigned short*)g_vh;
    unsigned short* VL = (unsigned short*)g_vl;
#pragma unroll
    for (int mi = 0; mi < 2; mi++) {
        int row = m0 + wm * 32 + mi * 16 + (lane >> 2);
#pragma unroll
        for (int ni = 0; ni < 8; ni++) {
#pragma unroll
            for (int cc = 0; cc < 2; cc++) {
                int col = n0 + wn * 64 + ni * 8 + (lane & 3) * 2 + cc;
                float s = g_kvs[col], t = g_kvt[col];
                int h = col / 80, r = col % 80;
                float y0 = c[mi][ni][cc] * s + t;
                float y1 = c[mi][ni][cc + 2] * s + t;
                if (r < 16) {
                    g_k[(size_t)row * 128 + h * 16 + r] = y0;
                    g_k[(size_t)(row + 8) * 128 + h * 16 + r] = y1;
                } else {
                    unsigned short hu, lu;
                    size_t i0 = (size_t)row * 512 + h * 64 + (r - 16);
                    size_t i1 = (size_t)(row + 8) * 512 + h * 64 + (r - 16);
                    splitbf(hswish(y0), hu, lu); VH[i0] = hu; VL[i0] = lu;
                    splitbf(hswish(y1), hu, lu); VH[i1] = hu; VL[i1] = lu;
                }
            }
        }
    }
}

// ---------------- kernel: attention + softmax + hswish -> bf16 (coalesced) ----------------
__global__ __launch_bounds__(1024) void k_attn(const float* __restrict__ biases) {
    const int h = blockIdx.x, b = blockIdx.y;
    const int tid = threadIdx.x;
    __shared__ float qs[NTOK * 16];
    __shared__ float bias_s[3200];
    __shared__ float red[32 * 10];
    __shared__ float bcast[10];

    float kr[16];
    const float4* kp = (const float4*)(g_k + (size_t)(b * NSEQ + tid) * 128 + h * 16);
#pragma unroll
    for (int i = 0; i < 4; i++) {
        float4 v = kp[i];
        kr[i * 4] = v.x; kr[i * 4 + 1] = v.y; kr[i * 4 + 2] = v.z; kr[i * 4 + 3] = v.w;
    }
    for (int i = tid; i < NTOK * 16; i += 1024) qs[i] = g_q[(i >> 4) * 128 + (i & 15) + h * 16];
    for (int i = tid; i < 3200; i += 1024) bias_s[i] = biases[h * 10000 + i];
    __syncthreads();

    const int p2x = tid >> 5, p2y = tid & 31;
    const int warp = tid >> 5, lane = tid & 31;
    __nv_bfloat16* AH = g_ah;
    size_t obase = ((size_t)(b * NHEAD + h) * NTOK) * NSEQ + tid;

    for (int t0 = 0; t0 < NTOK; t0 += 10) {
        float e[10];
#pragma unroll
        for (int cch = 0; cch < 10; cch++) {
            int t = t0 + cch;
            float logit = 0.f;
#pragma unroll
            for (int d = 0; d < 16; d++) logit += qs[t * 16 + d] * kr[d];
            int dy = t - p2y; if (dy < 0) dy = -dy;
            logit = logit * 0.25f + bias_s[p2x * 100 + dy];
            float ex = __expf(logit);
            e[cch] = ex;
            float s = ex;
#pragma unroll
            for (int o = 16; o > 0; o >>= 1) s += __shfl_xor_sync(0xffffffffu, s, o);
            if (lane == 0) red[warp * 10 + cch] = s;
        }
        __syncthreads();
        if (warp == 0) {
#pragma unroll
            for (int cch = 0; cch < 10; cch++) {
                float v = red[lane * 10 + cch];
#pragma unroll
                for (int o = 16; o > 0; o >>= 1) v += __shfl_xor_sync(0xffffffffu, v, o);
                if (lane == 0) bcast[cch] = v;
            }
        }
        __syncthreads();
#pragma unroll
        for (int cch = 0; cch < 10; cch++) {
            float p = e[cch] * __frcp_rn(bcast[cch]);
            float y = p * (p + 3.f) * (1.f / 6.f);
            AH[obase + (size_t)(t0 + cch) * NSEQ] = __float2bfloat16_rn(y);
        }
    }
}

// ---------------- kernel: proj GEMM (3-stage, single sync, swizzled; 1-term attn K-range) ----------------
__global__ __launch_bounds__(256) void k_proj_mma(float* __restrict__ out) {
    extern __shared__ __align__(128) unsigned char sm[];
    uint32_t s0 = smem_u32(sm);
    const int tid = threadIdx.x, lane = tid & 31, wid = tid >> 5;
    const int m0 = blockIdx.y * 128, n0 = blockIdx.x * 128;
    const int b = m0 >> 10, nbase = m0 & 1023;
    const int rowbase = b * 800;
    const int wm = wid >> 1, wn = wid & 1;
    const int arow = ((lane >> 3) & 1) * 8 + (lane & 7), acol = (lane >> 4) * 8;
    const int brow = (lane >> 4) * 8 + (lane & 7), bcol = ((lane >> 3) & 1) * 8;
    const __nv_bfloat16* pAH = g_vh + (size_t)m0 * 512;
    const __nv_bfloat16* pAL = g_vl + (size_t)m0 * 512;
    const __nv_bfloat16* pBH = g_pwh + (size_t)n0 * KEFF;
    const __nv_bfloat16* pBL = g_pwl + (size_t)n0 * KEFF;
    const unsigned short* GAH = (const unsigned short*)g_ah;
    float c[2][8][4] = {};

    auto LOAD = [&](int kc) {
        const int kt = kc * 32;
        const uint32_t sb = s0 + (kc % 3) * STG;
        unsigned char* smb = sm + (kc % 3) * STG;
        if (kt < 512) {
            // B hi+lo
#pragma unroll
            for (int i = 0; i < 4; i++) {
                int item = tid + i * 256;
                int arr = item >> 9, row = (item >> 2) & 127, c16 = item & 3;
                const __nv_bfloat16* src = (arr ? pBL : pBH) + (size_t)row * KEFF + kt + c16 * 8;
                cp16(sb + 16384 + arr * 8192 + swz(row, c16), src);
            }
            // A (v) hi+lo
#pragma unroll
            for (int i = 0; i < 4; i++) {
                int item = tid + i * 256;
                int arr = item >> 9, row = (item >> 2) & 127, c16 = item & 3;
                const __nv_bfloat16* src = (arr ? pAL : pAH) + (size_t)row * 512 + kt + c16 * 8;
                cp16(sb + arr * 8192 + swz(row, c16), src);
            }
        } else {
            // B hi only
#pragma unroll
            for (int i = 0; i < 2; i++) {
                int item = tid + i * 256;
                int row = item >> 2, c16 = item & 3;
                const __nv_bfloat16* src = pBH + (size_t)row * KEFF + kt + c16 * 8;
                cp16(sb + 16384 + swz(row, c16), src);
            }
            // A (attn) hi only: coalesced read + 2B transpose into swizzled tile
            const int kloc = kt - 512;
#pragma unroll
            for (int i = 0; i < 4; i++) {
                int item = tid + i * 256;
                int krow = item >> 5, nn = (item & 31) * 4;
                size_t idx = (size_t)(rowbase + kloc + krow) * NSEQ + nbase + nn;
                unsigned long long vh = *(const unsigned long long*)(GAH + idx);
                int kchunk = krow >> 3, kin = (krow & 7) * 2;
#pragma unroll
                for (int j = 0; j < 4; j++) {
                    *(unsigned short*)(smb + swz(nn + j, kchunk) + kin) =
                        (unsigned short)(vh >> (16 * j));
                }
            }
        }
    };

    LOAD(0); CP_COMMIT();
    LOAD(1); CP_COMMIT();
#pragma unroll 1
    for (int kc = 0; kc < 41; kc++) {
        if (kc < 40) { CP_WAIT1(); } else { CP_WAIT0(); }
        __syncthreads();
        if (kc < 16) mma_chunk32  (s0 + (kc % 3) * STG, wm, wn, arow, acol, brow, bcol, c);
        else         mma_chunk32_h(s0 + (kc % 3) * STG, wm, wn, arow, acol, brow, bcol, c);
        if (kc + 2 < 41) { LOAD(kc + 2); CP_COMMIT(); }
    }

    // epilogue: BN -> out
#pragma unroll
    for (int mi = 0; mi < 2; mi++) {
        int row = m0 + wm * 32 + mi * 16 + (lane >> 2);
#pragma unroll
        for (int ni = 0; ni < 8; ni++) {
#pragma unroll
            for (int cc = 0; cc < 2; cc++) {
                int col = n0 + wn * 64 + ni * 8 + (lane & 3) * 2 + cc;
                float s = g_psA[col], t = g_ptA[col];
                out[(size_t)row * DIMC + col]       = c[mi][ni][cc] * s + t;
                out[(size_t)(row + 8) * DIMC + col] = c[mi][ni][cc + 2] * s + t;
            }
        }
    }
}

// ---------------- launch ----------------
extern "C" void kernel_launch(void* const* d_in, const int* in_sizes, int n_in,
                              void* d_out, int out_size) {
    const float* x      = (const float*)d_in[0];
    const float* text   = (const float*)d_in[1];
    const float* kv_w   = (const float*)d_in[2];
    const float* kv_g   = (const float*)d_in[3];
    const float* kv_b   = (const float*)d_in[4];
    const float* kv_m   = (const float*)d_in[5];
    const float* kv_v   = (const float*)d_in[6];
    const float* q_w    = (const float*)d_in[7];
    const float* q_g    = (const float*)d_in[8];
    const float* q_b    = (const float*)d_in[9];
    const float* q_m    = (const float*)d_in[10];
    const float* q_v    = (const float*)d_in[11];
    const float* proj_w = (const float*)d_in[12];
    const float* proj_g = (const float*)d_in[13];
    const float* proj_b = (const float*)d_in[14];
    const float* proj_m = (const float*)d_in[15];
    const float* proj_v = (const float*)d_in[16];
    const float* biases = (const float*)d_in[17];
    float* out = (float*)d_out;

    cudaFuncSetAttribute(k_kv_mma,   cudaFuncAttributeMaxDynamicSharedMemorySize, DSMEM);
    cudaFuncSetAttribute(k_proj_mma, cudaFuncAttributeMaxDynamicSharedMemorySize, DSMEM);

    k_prep_bn<<<4, 256>>>(kv_g, kv_b, kv_m, kv_v, q_g, q_b, q_m, q_v,
                          proj_g, proj_b, proj_m, proj_v);
    k_split_x<<<(MTOT * DIMC / 4 + 255) / 256, 256>>>(x);
    k_split_kw<<<(HKV * DIMC / 4 + 255) / 256, 256>>>(kv_w);
    k_split_pw<<<(DIMC * (KEFF / 4) + 255) / 256, 256>>>(proj_w);
    k_qproj<<<50, 256>>>(text, q_w);
    k_kv_mma<<<dim3(HKV / 128, MTOT / 128), 256, DSMEM>>>();
    k_attn<<<dim3(NHEAD, BB), 1024>>>(biases);
    k_proj_mma<<<dim3(2, MTOT / 128), 256, DSMEM>>>(out);
}

// round 15
// speedup vs baseline: 1.4346x; 1.1384x over previous
#include <cuda_runtime.h>
#include <cuda_bf16.h>
#include <cstdint>

// ---------------- problem constants ----------------
#define BB    64
#define NSEQ  1024
#define NTOK  100
#define DIMC  256
#define NHEAD 8
#define HKV   640
#define PROJIN 1512
#define KEFF  1312
#define EPSV  1e-5f
#define MTOT  (BB*NSEQ)

// ---------------- scratch ----------------
__device__ float g_q[NTOK * 128];
__device__ float g_k[(size_t)MTOT * 128];
__device__ __nv_bfloat16 g_xh[(size_t)MTOT * DIMC];
__device__ __nv_bfloat16 g_xl[(size_t)MTOT * DIMC];
__device__ __nv_bfloat16 g_kwh[HKV * DIMC];
__device__ __nv_bfloat16 g_kwl[HKV * DIMC];
__device__ __nv_bfloat16 g_pwh[DIMC * KEFF];
__device__ __nv_bfloat16 g_pwl[DIMC * KEFF];
__device__ __nv_bfloat16 g_vh[(size_t)MTOT * 512];
__device__ __nv_bfloat16 g_vl[(size_t)MTOT * 512];
__device__ __nv_bfloat16 g_at[(size_t)MTOT * 800];   // hswish(p), bf16, feature-major (bn, h*100+t)
__device__ float g_kvs[HKV], g_kvt[HKV];
__device__ float g_qsA[128], g_qtA[128];
__device__ float g_psA[DIMC], g_ptA[DIMC];

__device__ __forceinline__ float hswish(float y) {
    return y * fminf(fmaxf(y + 3.f, 0.f), 6.f) * (1.f / 6.f);
}
__device__ __forceinline__ uint32_t smem_u32(const void* p) {
    uint32_t a;
    asm("{ .reg .u64 t; cvta.to.shared.u64 t, %1; cvt.u32.u64 %0, t; }" : "=r"(a) : "l"(p));
    return a;
}
__device__ __forceinline__ void split4(float4 v, unsigned long long& H, unsigned long long& L) {
    float f[4] = {v.x, v.y, v.z, v.w};
    unsigned long long h = 0, l = 0;
#pragma unroll
    for (int i = 0; i < 4; i++) {
        __nv_bfloat16 hb = __float2bfloat16_rn(f[i]);
        float r = f[i] - __bfloat162float(hb);
        __nv_bfloat16 lb = __float2bfloat16_rn(r);
        h |= (unsigned long long)__bfloat16_as_ushort(hb) << (16 * i);
        l |= (unsigned long long)__bfloat16_as_ushort(lb) << (16 * i);
    }
    H = h; L = l;
}
__device__ __forceinline__ void splitbf(float y, unsigned short& hu, unsigned short& lu) {
    __nv_bfloat16 hb = __float2bfloat16_rn(y);
    float r = y - __bfloat162float(hb);
    __nv_bfloat16 lb = __float2bfloat16_rn(r);
    hu = __bfloat16_as_ushort(hb); lu = __bfloat16_as_ushort(lb);
}

// ---------------- warp-mma + cp.async primitives ----------------
__device__ __forceinline__ void ldsm4(uint32_t addr, uint32_t* r) {
    asm volatile("ldmatrix.sync.aligned.m8n8.x4.shared.b16 {%0,%1,%2,%3}, [%4];"
                 : "=r"(r[0]), "=r"(r[1]), "=r"(r[2]), "=r"(r[3]) : "r"(addr));
}
__device__ __forceinline__ void mma16816(float* c, const uint32_t* a, uint32_t b0, uint32_t b1) {
    asm volatile("mma.sync.aligned.m16n8k16.row.col.f32.bf16.bf16.f32 "
                 "{%0,%1,%2,%3}, {%4,%5,%6,%7}, {%8,%9}, {%0,%1,%2,%3};"
                 : "+f"(c[0]), "+f"(c[1]), "+f"(c[2]), "+f"(c[3])
                 : "r"(a[0]), "r"(a[1]), "r"(a[2]), "r"(a[3]), "r"(b0), "r"(b1));
}
__device__ __forceinline__ void cp16(uint32_t s, const void* g) {
    asm volatile("cp.async.cg.shared.global [%0], [%1], 16;" :: "r"(s), "l"(g));
}
#define CP_COMMIT() asm volatile("cp.async.commit_group;" ::: "memory")
#define CP_WAIT0()  asm volatile("cp.async.wait_group 0;" ::: "memory")
#define CP_WAIT1()  asm volatile("cp.async.wait_group 1;" ::: "memory")

// Swizzled tile: pitch 64B, 16B-chunk XOR (row>>1)&3. Tiles: AH@0, AL@8192, BH@16384, BL@24576.
#define STG   32768
#define DSMEM (3*STG)
__device__ __forceinline__ uint32_t swz(int row, int c16) {
    return (uint32_t)(row * 64 + ((c16 ^ ((row >> 1) & 3)) << 4));
}

// 3-term chunk, warp tile 32x64
__device__ __forceinline__ void mma_chunk32(uint32_t sb, int wm, int wn,
                                            int arow, int acol, int brow, int bcol,
                                            float c[2][8][4]) {
#pragma unroll
    for (int ks = 0; ks < 32; ks += 16) {
        uint32_t ah0[4], ah1[4], al0[4], al1[4];
        int ar0 = wm * 32 + arow;
        int ac = (ks + acol) >> 3;
        ldsm4(sb + swz(ar0, ac), ah0);
        ldsm4(sb + swz(ar0 + 16, ac), ah1);
        ldsm4(sb + 8192 + swz(ar0, ac), al0);
        ldsm4(sb + 8192 + swz(ar0 + 16, ac), al1);
#pragma unroll
        for (int np = 0; np < 4; np++) {
            uint32_t bh[4], bl[4];
            int br = wn * 64 + np * 16 + brow;
            int bc = (ks + bcol) >> 3;
            ldsm4(sb + 16384 + swz(br, bc), bh);
            ldsm4(sb + 24576 + swz(br, bc), bl);
            mma16816(c[0][np * 2],     ah0, bh[0], bh[1]);
            mma16816(c[1][np * 2],     ah1, bh[0], bh[1]);
            mma16816(c[0][np * 2 + 1], ah0, bh[2], bh[3]);
            mma16816(c[1][np * 2 + 1], ah1, bh[2], bh[3]);
            mma16816(c[0][np * 2],     al0, bh[0], bh[1]);
            mma16816(c[1][np * 2],     al1, bh[0], bh[1]);
            mma16816(c[0][np * 2 + 1], al0, bh[2], bh[3]);
            mma16816(c[1][np * 2 + 1], al1, bh[2], bh[3]);
            mma16816(c[0][np * 2],     ah0, bl[0], bl[1]);
            mma16816(c[1][np * 2],     ah1, bl[0], bl[1]);
            mma16816(c[0][np * 2 + 1], ah0, bl[2], bl[3]);
            mma16816(c[1][np * 2 + 1], ah1, bl[2], bl[3]);
        }
    }
}

// 1-term chunk (Ah*Bh only)
__device__ __forceinline__ void mma_chunk32_h(uint32_t sb, int wm, int wn,
                                              int arow, int acol, int brow, int bcol,
                                              float c[2][8][4]) {
#pragma unroll
    for (int ks = 0; ks < 32; ks += 16) {
        uint32_t ah0[4], ah1[4];
        int ar0 = wm * 32 + arow;
        int ac = (ks + acol) >> 3;
        ldsm4(sb + swz(ar0, ac), ah0);
        ldsm4(sb + swz(ar0 + 16, ac), ah1);
#pragma unroll
        for (int np = 0; np < 4; np++) {
            uint32_t bh[4];
            int br = wn * 64 + np * 16 + brow;
            int bc = (ks + bcol) >> 3;
            ldsm4(sb + 16384 + swz(br, bc), bh);
            mma16816(c[0][np * 2],     ah0, bh[0], bh[1]);
            mma16816(c[1][np * 2],     ah1, bh[0], bh[1]);
            mma16816(c[0][np * 2 + 1], ah0, bh[2], bh[3]);
            mma16816(c[1][np * 2 + 1], ah1, bh[2], bh[3]);
        }
    }
}

// ---------------- prep kernels ----------------
__global__ void k_prep_bn(const float* kg, const float* kb, const float* km, const float* kv,
                          const float* qg, const float* qb, const float* qm, const float* qv,
                          const float* pg, const float* pb, const float* pm, const float* pv) {
    int i = blockIdx.x * 256 + threadIdx.x;
    if (i < HKV) {
        float s = kg[i] * rsqrtf(kv[i] + EPSV);
        g_kvs[i] = s; g_kvt[i] = kb[i] - km[i] * s;
    } else if (i < HKV + 128) {
        int j = i - HKV;
        float s = qg[j] * rsqrtf(qv[j] + EPSV);
        g_qsA[j] = s; g_qtA[j] = qb[j] - qm[j] * s;
    } else if (i < HKV + 128 + DIMC) {
        int j = i - HKV - 128;
        float s = pg[j] * rsqrtf(pv[j] + EPSV);
        g_psA[j] = s; g_ptA[j] = pb[j] - pm[j] * s;
    }
}
__global__ void k_split_x(const float* __restrict__ src) {
    int i = blockIdx.x * 256 + threadIdx.x;
    if (i >= MTOT * DIMC / 4) return;
    float4 v = ((const float4*)src)[i];
    unsigned long long H, L; split4(v, H, L);
    ((unsigned long long*)g_xh)[i] = H;
    ((unsigned long long*)g_xl)[i] = L;
}
__global__ void k_split_kw(const float* __restrict__ src) {
    int i = blockIdx.x * 256 + threadIdx.x;
    if (i >= HKV * DIMC / 4) return;
    float4 v = ((const float4*)src)[i];
    unsigned long long H, L; split4(v, H, L);
    ((unsigned long long*)g_kwh)[i] = H;
    ((unsigned long long*)g_kwl)[i] = L;
}
__global__ void k_split_pw(const float* __restrict__ src) {
    int i = blockIdx.x * 256 + threadIdx.x;
    if (i >= DIMC * (KEFF / 4)) return;
    int r = i / (KEFF / 4), c = i % (KEFF / 4);
    float4 v = *(const float4*)(src + (size_t)r * PROJIN + c * 4);
    unsigned long long H, L; split4(v, H, L);
    ((unsigned long long*)g_pwh)[i] = H;
    ((unsigned long long*)g_pwl)[i] = L;
}

// ---------------- kernel: q projection + BN ----------------
__global__ void k_qproj(const float* __restrict__ text, const float* __restrict__ qw) {
    int o = blockIdx.x * blockDim.x + threadIdx.x;
    if (o >= NTOK * 128) return;
    int t = o >> 7, col = o & 127;
    const float4* tr = (const float4*)(text + t * DIMC);
    const float4* wr = (const float4*)(qw + col * DIMC);
    float acc = 0.f;
#pragma unroll 16
    for (int k = 0; k < DIMC / 4; k++) {
        float4 a = tr[k], w = wr[k];
        acc += a.x * w.x + a.y * w.y + a.z * w.z + a.w * w.w;
    }
    g_q[o] = acc * g_qsA[col] + g_qtA[col];
}

// ---------------- kernel: kv GEMM (3-stage, single sync per chunk, swizzled tiles) ----------------
__global__ __launch_bounds__(256) void k_kv_mma() {
    extern __shared__ __align__(128) unsigned char sm[];
    uint32_t s0 = smem_u32(sm);
    const int tid = threadIdx.x, lane = tid & 31, wid = tid >> 5;
    const int m0 = blockIdx.y * 128, n0 = blockIdx.x * 128;
    const int wm = wid >> 1, wn = wid & 1;
    const int arow = ((lane >> 3) & 1) * 8 + (lane & 7), acol = (lane >> 4) * 8;
    const int brow = (lane >> 4) * 8 + (lane & 7), bcol = ((lane >> 3) & 1) * 8;
    const __nv_bfloat16* pAH = g_xh + (size_t)m0 * DIMC;
    const __nv_bfloat16* pAL = g_xl + (size_t)m0 * DIMC;
    const __nv_bfloat16* pBH = g_kwh + (size_t)n0 * DIMC;
    const __nv_bfloat16* pBL = g_kwl + (size_t)n0 * DIMC;
    float c[2][8][4] = {};

    auto LOAD = [&](int kc) {
        const int kt = kc * 32;
        const uint32_t sb = s0 + (kc % 3) * STG;
#pragma unroll
        for (int i = 0; i < 8; i++) {
            int item = tid + i * 256;
            int ab = item >> 10, arr = (item >> 9) & 1, row = (item >> 2) & 127, c16 = item & 3;
            const __nv_bfloat16* src = ab ? (arr ? pBL : pBH) : (arr ? pAL : pAH);
            src += (size_t)row * DIMC + kt + c16 * 8;
            cp16(sb + ab * 16384 + arr * 8192 + swz(row, c16), src);
        }
    };

    LOAD(0); CP_COMMIT();
    LOAD(1); CP_COMMIT();
#pragma unroll 1
    for (int kc = 0; kc < 8; kc++) {
        if (kc < 7) { CP_WAIT1(); } else { CP_WAIT0(); }
        __syncthreads();
        mma_chunk32(s0 + (kc % 3) * STG, wm, wn, arow, acol, brow, bcol, c);
        if (kc + 2 < 8) { LOAD(kc + 2); CP_COMMIT(); }
    }

    unsigned short* VH = (unsigned short*)g_vh;
    unsigned short* VL = (unsigned short*)g_vl;
#pragma unroll
    for (int mi = 0; mi < 2; mi++) {
        int row = m0 + wm * 32 + mi * 16 + (lane >> 2);
#pragma unroll
        for (int ni = 0; ni < 8; ni++) {
#pragma unroll
            for (int cc = 0; cc < 2; cc++) {
                int col = n0 + wn * 64 + ni * 8 + (lane & 3) * 2 + cc;
                float s = g_kvs[col], t = g_kvt[col];
                int h = col / 80, r = col % 80;
                float y0 = c[mi][ni][cc] * s + t;
                float y1 = c[mi][ni][cc + 2] * s + t;
                if (r < 16) {
                    g_k[(size_t)row * 128 + h * 16 + r] = y0;
                    g_k[(size_t)(row + 8) * 128 + h * 16 + r] = y1;
                } else {
                    unsigned short hu, lu;
                    size_t i0 = (size_t)row * 512 + h * 64 + (r - 16);
                    size_t i1 = (size_t)(row + 8) * 512 + h * 64 + (r - 16);
                    splitbf(hswish(y0), hu, lu); VH[i0] = hu; VL[i0] = lu;
                    splitbf(hswish(y1), hu, lu); VH[i1] = hu; VL[i1] = lu;
                }
            }
        }
    }
}

// ---------------- kernel: attention + softmax + hswish -> bf16, FEATURE-MAJOR (bn, h*100+t) ----------------
// Each thread owns one n; its output segment [bn][h*100 .. h*100+99] is 200 contiguous bytes,
// written as 5 packed uint32 per 10-t chunk (no 2B scatter).
__global__ __launch_bounds__(1024) void k_attn(const float* __restrict__ biases) {
    const int h = blockIdx.x, b = blockIdx.y;
    const int tid = threadIdx.x;
    __shared__ float qs[NTOK * 16];
    __shared__ float bias_s[3200];
    __shared__ float red[32 * 10];
    __shared__ float bcast[10];

    float kr[16];
    const float4* kp = (const float4*)(g_k + (size_t)(b * NSEQ + tid) * 128 + h * 16);
#pragma unroll
    for (int i = 0; i < 4; i++) {
        float4 v = kp[i];
        kr[i * 4] = v.x; kr[i * 4 + 1] = v.y; kr[i * 4 + 2] = v.z; kr[i * 4 + 3] = v.w;
    }
    for (int i = tid; i < NTOK * 16; i += 1024) qs[i] = g_q[(i >> 4) * 128 + (i & 15) + h * 16];
    for (int i = tid; i < 3200; i += 1024) bias_s[i] = biases[h * 10000 + i];
    __syncthreads();

    const int p2x = tid >> 5, p2y = tid & 31;
    const int warp = tid >> 5, lane = tid & 31;
    unsigned short* AT = (unsigned short*)g_at;
    size_t obase = (size_t)(b * NSEQ + tid) * 800 + h * 100;   // even ushort index -> uint-aligned

    for (int t0 = 0; t0 < NTOK; t0 += 10) {
        float e[10];
#pragma unroll
        for (int cch = 0; cch < 10; cch++) {
            int t = t0 + cch;
            float logit = 0.f;
#pragma unroll
            for (int d = 0; d < 16; d++) logit += qs[t * 16 + d] * kr[d];
            int dy = t - p2y; if (dy < 0) dy = -dy;
            logit = logit * 0.25f + bias_s[p2x * 100 + dy];
            float ex = __expf(logit);
            e[cch] = ex;
            float s = ex;
#pragma unroll
            for (int o = 16; o > 0; o >>= 1) s += __shfl_xor_sync(0xffffffffu, s, o);
            if (lane == 0) red[warp * 10 + cch] = s;
        }
        __syncthreads();
        if (warp == 0) {
#pragma unroll
            for (int cch = 0; cch < 10; cch++) {
                float v = red[lane * 10 + cch];
#pragma unroll
                for (int o = 16; o > 0; o >>= 1) v += __shfl_xor_sync(0xffffffffu, v, o);
                if (lane == 0) bcast[cch] = v;
            }
        }
        __syncthreads();
        uint32_t* dst = (uint32_t*)(AT + obase + t0);
#pragma unroll
        for (int j = 0; j < 5; j++) {
            float p0 = e[2 * j]     * __frcp_rn(bcast[2 * j]);
            float p1 = e[2 * j + 1] * __frcp_rn(bcast[2 * j + 1]);
            float y0 = p0 * (p0 + 3.f) * (1.f / 6.f);
            float y1 = p1 * (p1 + 3.f) * (1.f / 6.f);
            uint32_t pk = (uint32_t)__bfloat16_as_ushort(__float2bfloat16_rn(y0))
                        | ((uint32_t)__bfloat16_as_ushort(__float2bfloat16_rn(y1)) << 16);
            dst[j] = pk;
        }
    }
}

// ---------------- kernel: proj GEMM (uniform cp.async pipeline; 1-term attn K-range) ----------------
__global__ __launch_bounds__(256) void k_proj_mma(float* __restrict__ out) {
    extern __shared__ __align__(128) unsigned char sm[];
    uint32_t s0 = smem_u32(sm);
    const int tid = threadIdx.x, lane = tid & 31, wid = tid >> 5;
    const int m0 = blockIdx.y * 128, n0 = blockIdx.x * 128;
    const int wm = wid >> 1, wn = wid & 1;
    const int arow = ((lane >> 3) & 1) * 8 + (lane & 7), acol = (lane >> 4) * 8;
    const int brow = (lane >> 4) * 8 + (lane & 7), bcol = ((lane >> 3) & 1) * 8;
    const __nv_bfloat16* pAH = g_vh + (size_t)m0 * 512;
    const __nv_bfloat16* pAL = g_vl + (size_t)m0 * 512;
    const __nv_bfloat16* pAT = g_at + (size_t)m0 * 800;
    const __nv_bfloat16* pBH = g_pwh + (size_t)n0 * KEFF;
    const __nv_bfloat16* pBL = g_pwl + (size_t)n0 * KEFF;
    float c[2][8][4] = {};

    auto LOAD = [&](int kc) {
        const int kt = kc * 32;
        const uint32_t sb = s0 + (kc % 3) * STG;
        if (kt < 512) {
            // B hi+lo
#pragma unroll
            for (int i = 0; i < 4; i++) {
                int item = tid + i * 256;
                int arr = item >> 9, row = (item >> 2) & 127, c16 = item & 3;
                const __nv_bfloat16* src = (arr ? pBL : pBH) + (size_t)row * KEFF + kt + c16 * 8;
                cp16(sb + 16384 + arr * 8192 + swz(row, c16), src);
            }
            // A (v) hi+lo
#pragma unroll
            for (int i = 0; i < 4; i++) {
                int item = tid + i * 256;
                int arr = item >> 9, row = (item >> 2) & 127, c16 = item & 3;
                const __nv_bfloat16* src = (arr ? pAL : pAH) + (size_t)row * 512 + kt + c16 * 8;
                cp16(sb + arr * 8192 + swz(row, c16), src);
            }
        } else {
            const int kloc = kt - 512;
            // B hi only
#pragma unroll
            for (int i = 0; i < 2; i++) {
                int item = tid + i * 256;
                int row = item >> 2, c16 = item & 3;
                const __nv_bfloat16* src = pBH + (size_t)row * KEFF + kt + c16 * 8;
                cp16(sb + 16384 + swz(row, c16), src);
            }
            // A (attn) hi only — now a plain strided cp.async from feature-major g_at
#pragma unroll
            for (int i = 0; i < 2; i++) {
                int item = tid + i * 256;
                int row = item >> 2, c16 = item & 3;
                const __nv_bfloat16* src = pAT + (size_t)row * 800 + kloc + c16 * 8;
                cp16(sb + swz(row, c16), src);
            }
        }
    };

    LOAD(0); CP_COMMIT();
    LOAD(1); CP_COMMIT();
#pragma unroll 1
    for (int kc = 0; kc < 41; kc++) {
        if (kc < 40) { CP_WAIT1(); } else { CP_WAIT0(); }
        __syncthreads();
        if (kc < 16) mma_chunk32  (s0 + (kc % 3) * STG, wm, wn, arow, acol, brow, bcol, c);
        else         mma_chunk32_h(s0 + (kc % 3) * STG, wm, wn, arow, acol, brow, bcol, c);
        if (kc + 2 < 41) { LOAD(kc + 2); CP_COMMIT(); }
    }

    // epilogue: BN -> out
#pragma unroll
    for (int mi = 0; mi < 2; mi++) {
        int row = m0 + wm * 32 + mi * 16 + (lane >> 2);
#pragma unroll
        for (int ni = 0; ni < 8; ni++) {
#pragma unroll
            for (int cc = 0; cc < 2; cc++) {
                int col = n0 + wn * 64 + ni * 8 + (lane & 3) * 2 + cc;
                float s = g_psA[col], t = g_ptA[col];
                out[(size_t)row * DIMC + col]       = c[mi][ni][cc] * s + t;
                out[(size_t)(row + 8) * DIMC + col] = c[mi][ni][cc + 2] * s + t;
            }
        }
    }
}

// ---------------- launch ----------------
extern "C" void kernel_launch(void* const* d_in, const int* in_sizes, int n_in,
                              void* d_out, int out_size) {
    const float* x      = (const float*)d_in[0];
    const float* text   = (const float*)d_in[1];
    const float* kv_w   = (const float*)d_in[2];
    const float* kv_g   = (const float*)d_in[3];
    const float* kv_b   = (const float*)d_in[4];
    const float* kv_m   = (const float*)d_in[5];
    const float* kv_v   = (const float*)d_in[6];
    const float* q_w    = (const float*)d_in[7];
    const float* q_g    = (const float*)d_in[8];
    const float* q_b    = (const float*)d_in[9];
    const float* q_m    = (const float*)d_in[10];
    const float* q_v    = (const float*)d_in[11];
    const float* proj_w = (const float*)d_in[12];
    const float* proj_g = (const float*)d_in[13];
    const float* proj_b = (const float*)d_in[14];
    const float* proj_m = (const float*)d_in[15];
    const float* proj_v = (const float*)d_in[16];
    const float* biases = (const float*)d_in[17];
    float* out = (float*)d_out;

    cudaFuncSetAttribute(k_kv_mma,   cudaFuncAttributeMaxDynamicSharedMemorySize, DSMEM);
    cudaFuncSetAttribute(k_proj_mma, cudaFuncAttributeMaxDynamicSharedMemorySize, DSMEM);

    k_prep_bn<<<4, 256>>>(kv_g, kv_b, kv_m, kv_v, q_g, q_b, q_m, q_v,
                          proj_g, proj_b, proj_m, proj_v);
    k_split_x<<<(MTOT * DIMC / 4 + 255) / 256, 256>>>(x);
    k_split_kw<<<(HKV * DIMC / 4 + 255) / 256, 256>>>(kv_w);
    k_split_pw<<<(DIMC * (KEFF / 4) + 255) / 256, 256>>>(proj_w);
    k_qproj<<<50, 256>>>(text, q_w);
    k_kv_mma<<<dim3(HKV / 128, MTOT / 128), 256, DSMEM>>>();
    k_attn<<<dim3(NHEAD, BB), 1024>>>(biases);
    k_proj_mma<<<dim3(2, MTOT / 128), 256, DSMEM>>>(out);
}